// round 4
// baseline (speedup 1.0000x reference)
#include <cuda_runtime.h>
#include <math.h>
#include <stdint.h>

// Problem dims (fixed by the benchmark)
#define D_MODEL 768
#define NH      12
#define HDIM    64
#define C_CLS   50
#define S_SYN   4
#define B_BATCH 4
#define T_LEN   1024
#define R_ROWS  (C_CLS * S_SYN)      // 200
#define BZ      (B_BATCH * NH)       // 48

// -------- scratch (no allocation allowed) --------
__device__ float g_qproj[R_ROWS * D_MODEL];            // (c*4+s, d)
__device__ float g_kproj[B_BATCH * T_LEN * D_MODEL];   // tanh(H@WK+b)
__device__ float g_ktanh[B_BATCH * T_LEN * D_MODEL];   // tanh(H)
__device__ float g_wql [C_CLS * D_MODEL];              // ql@WV+b
__device__ float g_scores[BZ * R_ROWS * T_LEN];        // per (b,z): [200,1024]
__device__ float g_w  [BZ * C_CLS * T_LEN];            // combined softmax weights
__device__ float g_m2 [BZ * T_LEN * C_CLS];            // per (b,z): [1024,50]

// ============================================================
// tf32 helpers
// ============================================================
__device__ __forceinline__ void split_tf32(float x, uint32_t& hi, uint32_t& lo) {
    uint32_t h;
    asm("cvt.rna.tf32.f32 %0, %1;" : "=r"(h) : "f"(x));
    float l = x - __uint_as_float(h);
    uint32_t lb;
    asm("cvt.rna.tf32.f32 %0, %1;" : "=r"(lb) : "f"(l));
    hi = h; lo = lb;
}

__device__ __forceinline__ void split4(float4 v, uint32_t* hi, uint32_t* lo) {
    split_tf32(v.x, hi[0], lo[0]);
    split_tf32(v.y, hi[1], lo[1]);
    split_tf32(v.z, hi[2], lo[2]);
    split_tf32(v.w, hi[3], lo[3]);
}

__device__ __forceinline__ void mma_tf32(float* c, const uint32_t* a, const uint32_t* b) {
    asm volatile(
        "mma.sync.aligned.m16n8k8.row.col.f32.tf32.tf32.f32 "
        "{%0,%1,%2,%3}, {%4,%5,%6,%7}, {%8,%9}, {%0,%1,%2,%3};"
        : "+f"(c[0]), "+f"(c[1]), "+f"(c[2]), "+f"(c[3])
        : "r"(a[0]), "r"(a[1]), "r"(a[2]), "r"(a[3]), "r"(b[0]), "r"(b[1]));
}

// ============================================================
// Projection GEMM (3xTF32, pre-split smem, prefetched):
//   C[M,N] = act(A[M,K] @ B[K,N] + bias[N])
// Block 128x128, BK=32, 256 threads = 8 warps (4x2), warp tile 32x64.
// N,K multiples of 128/32. M ragged. Dynamic smem = 71680 B.
// ============================================================
#define ASTR 36
#define BSTR 136
#define GEMM_SMEM ((2 * 128 * ASTR + 2 * 32 * BSTR) * 4)

template <int ACT>
__global__ void __launch_bounds__(256) gemm_tf32_kernel(
    const float* __restrict__ A, const float* __restrict__ B,
    const float* __restrict__ bias, float* __restrict__ C,
    int M, int N, int K)
{
    extern __shared__ uint32_t sm[];
    uint32_t* As_hi = sm;                       // [128][ASTR]
    uint32_t* As_lo = As_hi + 128 * ASTR;
    uint32_t* Bs_hi = As_lo + 128 * ASTR;       // [32][BSTR]
    uint32_t* Bs_lo = Bs_hi + 32 * BSTR;

    const int tid  = threadIdx.x;
    const int warp = tid >> 5, lane = tid & 31;
    const int wm = (warp >> 1) * 32;
    const int wn = (warp & 1) * 64;
    const int bm = blockIdx.y * 128, bn = blockIdx.x * 128;
    const int lrow = lane >> 2, lcol = lane & 3;

    float acc[2][8][4];
#pragma unroll
    for (int mi = 0; mi < 2; mi++)
#pragma unroll
        for (int ni = 0; ni < 8; ni++)
#pragma unroll
            for (int q = 0; q < 4; q++) acc[mi][ni][q] = 0.f;

    const int ar = tid >> 1, ac = (tid & 1) * 16;   // A: row 0..127, col 0/16
    const int br = tid >> 3, bc = (tid & 7) * 4;    // B: row 0..31, col 0..28
    const bool arok = (bm + ar) < M;

    float4 av[4], bv[4];
#pragma unroll
    for (int i = 0; i < 4; i++) {
        av[i] = arok ? *(const float4*)&A[(size_t)(bm + ar) * K + ac + i * 4]
                     : make_float4(0.f, 0.f, 0.f, 0.f);
        bv[i] = *(const float4*)&B[(size_t)br * N + bn + bc + i * 32];
    }

    for (int k0 = 0; k0 < K; k0 += 32) {
        // split current regs into smem
#pragma unroll
        for (int i = 0; i < 4; i++) {
            uint32_t hi[4], lo[4];
            split4(av[i], hi, lo);
            *(uint4*)&As_hi[ar * ASTR + ac + i * 4] = *(uint4*)hi;
            *(uint4*)&As_lo[ar * ASTR + ac + i * 4] = *(uint4*)lo;
            split4(bv[i], hi, lo);
            *(uint4*)&Bs_hi[br * BSTR + bc + i * 32] = *(uint4*)hi;
            *(uint4*)&Bs_lo[br * BSTR + bc + i * 32] = *(uint4*)lo;
        }
        __syncthreads();

        // prefetch next tile
        if (k0 + 32 < K) {
#pragma unroll
            for (int i = 0; i < 4; i++) {
                av[i] = arok ? *(const float4*)&A[(size_t)(bm + ar) * K + k0 + 32 + ac + i * 4]
                             : make_float4(0.f, 0.f, 0.f, 0.f);
                bv[i] = *(const float4*)&B[(size_t)(k0 + 32 + br) * N + bn + bc + i * 32];
            }
        }

#pragma unroll
        for (int ks = 0; ks < 32; ks += 8) {
            uint32_t ahi[2][4], alo[2][4];
#pragma unroll
            for (int mi = 0; mi < 2; mi++) {
                const int r0 = wm + mi * 16 + lrow;
                const int kc = ks + lcol;
                ahi[mi][0] = As_hi[r0 * ASTR + kc];
                alo[mi][0] = As_lo[r0 * ASTR + kc];
                ahi[mi][1] = As_hi[(r0 + 8) * ASTR + kc];
                alo[mi][1] = As_lo[(r0 + 8) * ASTR + kc];
                ahi[mi][2] = As_hi[r0 * ASTR + kc + 4];
                alo[mi][2] = As_lo[r0 * ASTR + kc + 4];
                ahi[mi][3] = As_hi[(r0 + 8) * ASTR + kc + 4];
                alo[mi][3] = As_lo[(r0 + 8) * ASTR + kc + 4];
            }
#pragma unroll
            for (int ni = 0; ni < 8; ni++) {
                const int col = wn + ni * 8 + lrow;
                const int kr = ks + lcol;
                uint32_t bhi[2], blo[2];
                bhi[0] = Bs_hi[kr * BSTR + col];
                blo[0] = Bs_lo[kr * BSTR + col];
                bhi[1] = Bs_hi[(kr + 4) * BSTR + col];
                blo[1] = Bs_lo[(kr + 4) * BSTR + col];
#pragma unroll
                for (int mi = 0; mi < 2; mi++) {
                    mma_tf32(acc[mi][ni], ahi[mi], blo);
                    mma_tf32(acc[mi][ni], alo[mi], bhi);
                    mma_tf32(acc[mi][ni], ahi[mi], bhi);
                }
            }
        }
        __syncthreads();
    }

#pragma unroll
    for (int mi = 0; mi < 2; mi++) {
        const int row = bm + wm + mi * 16 + lrow;
#pragma unroll
        for (int ni = 0; ni < 8; ni++) {
            const int col = bn + wn + ni * 8 + lcol * 2;
            const float b0 = bias[col], b1 = bias[col + 1];
            if (row < M) {
                float v0 = acc[mi][ni][0] + b0, v1 = acc[mi][ni][1] + b1;
                if (ACT == 1) { v0 = tanhf(v0); v1 = tanhf(v1); }
                *(float2*)&C[(size_t)row * N + col] = make_float2(v0, v1);
            }
            if (row + 8 < M) {
                float v2 = acc[mi][ni][2] + b0, v3 = acc[mi][ni][3] + b1;
                if (ACT == 1) { v2 = tanhf(v2); v3 = tanhf(v3); }
                *(float2*)&C[(size_t)(row + 8) * N + col] = make_float2(v2, v3);
            }
        }
    }
}

// ============================================================
// Scores GEMM on tensor cores (3xTF32):
//  per bz: C[m,t] = sum_{h<64} qproj[m, z*64+h] * kproj[b,t, z*64+h]
// Block 64x128, BK=64 (single pass), 256 threads = 8 warps (2x4),
// warp tile 32x32. A and B both stored [row][k] (k-minor, stride 68).
// Dynamic smem = 104448 B.
// ============================================================
#define SSTR 68
#define SC_SMEM ((2 * 64 * SSTR + 2 * 128 * SSTR) * 4)

__global__ void __launch_bounds__(256) scores_tf32_kernel(
    const float* __restrict__ qproj, const float* __restrict__ kproj,
    float* __restrict__ scores)
{
    extern __shared__ uint32_t sm[];
    uint32_t* As_hi = sm;                        // [64][SSTR]  (m, h)
    uint32_t* As_lo = As_hi + 64 * SSTR;
    uint32_t* Bt_hi = As_lo + 64 * SSTR;         // [128][SSTR] (t, h)
    uint32_t* Bt_lo = Bt_hi + 128 * SSTR;

    const int bz = blockIdx.z;
    const int b = bz / NH, z = bz % NH;
    const float* Ab = qproj + (size_t)z * HDIM;
    const float* Bb = kproj + (size_t)b * T_LEN * D_MODEL + (size_t)z * HDIM;
    float* Cb = g_scores + (size_t)bz * R_ROWS * T_LEN;
    (void)scores;

    const int tid  = threadIdx.x;
    const int warp = tid >> 5, lane = tid & 31;
    const int wm = (warp >> 2) * 32;     // 2 warp-rows
    const int wn = (warp & 3) * 32;      // 4 warp-cols
    const int mbase = blockIdx.y * 64, nbase = blockIdx.x * 128;
    const int lrow = lane >> 2, lcol = lane & 3;

    // load A tile: 64 rows x 64 h
    {
        const int row = tid >> 2, colb = (tid & 3) * 16;
        const bool ok = (mbase + row) < R_ROWS;
#pragma unroll
        for (int i = 0; i < 4; i++) {
            float4 v = ok ? *(const float4*)&Ab[(size_t)(mbase + row) * D_MODEL + colb + i * 4]
                          : make_float4(0.f, 0.f, 0.f, 0.f);
            uint32_t hi[4], lo[4];
            split4(v, hi, lo);
            *(uint4*)&As_hi[row * SSTR + colb + i * 4] = *(uint4*)hi;
            *(uint4*)&As_lo[row * SSTR + colb + i * 4] = *(uint4*)lo;
        }
    }
    // load B tile: 128 rows (t) x 64 h, natural layout
    {
        const int r0 = tid >> 2, colb = (tid & 3) * 16;
#pragma unroll
        for (int half = 0; half < 2; half++) {
            const int row = r0 + half * 64;
#pragma unroll
            for (int i = 0; i < 4; i++) {
                float4 v = *(const float4*)&Bb[(size_t)(nbase + row) * D_MODEL + colb + i * 4];
                uint32_t hi[4], lo[4];
                split4(v, hi, lo);
                *(uint4*)&Bt_hi[row * SSTR + colb + i * 4] = *(uint4*)hi;
                *(uint4*)&Bt_lo[row * SSTR + colb + i * 4] = *(uint4*)lo;
            }
        }
    }
    __syncthreads();

    float acc[2][4][4];
#pragma unroll
    for (int mi = 0; mi < 2; mi++)
#pragma unroll
        for (int ni = 0; ni < 4; ni++)
#pragma unroll
            for (int q = 0; q < 4; q++) acc[mi][ni][q] = 0.f;

#pragma unroll
    for (int ks = 0; ks < 64; ks += 8) {
        uint32_t ahi[2][4], alo[2][4];
#pragma unroll
        for (int mi = 0; mi < 2; mi++) {
            const int r0 = wm + mi * 16 + lrow;
            const int kc = ks + lcol;
            ahi[mi][0] = As_hi[r0 * SSTR + kc];
            alo[mi][0] = As_lo[r0 * SSTR + kc];
            ahi[mi][1] = As_hi[(r0 + 8) * SSTR + kc];
            alo[mi][1] = As_lo[(r0 + 8) * SSTR + kc];
            ahi[mi][2] = As_hi[r0 * SSTR + kc + 4];
            alo[mi][2] = As_lo[r0 * SSTR + kc + 4];
            ahi[mi][3] = As_hi[(r0 + 8) * SSTR + kc + 4];
            alo[mi][3] = As_lo[(r0 + 8) * SSTR + kc + 4];
        }
#pragma unroll
        for (int ni = 0; ni < 4; ni++) {
            const int col = wn + ni * 8 + lrow;   // t index
            const int kr = ks + lcol;
            uint32_t bhi[2], blo[2];
            bhi[0] = Bt_hi[col * SSTR + kr];
            blo[0] = Bt_lo[col * SSTR + kr];
            bhi[1] = Bt_hi[col * SSTR + kr + 4];
            blo[1] = Bt_lo[col * SSTR + kr + 4];
#pragma unroll
            for (int mi = 0; mi < 2; mi++) {
                mma_tf32(acc[mi][ni], ahi[mi], blo);
                mma_tf32(acc[mi][ni], alo[mi], bhi);
                mma_tf32(acc[mi][ni], ahi[mi], bhi);
            }
        }
    }

#pragma unroll
    for (int mi = 0; mi < 2; mi++) {
        const int row = mbase + wm + mi * 16 + lrow;
#pragma unroll
        for (int ni = 0; ni < 4; ni++) {
            const int col = nbase + wn + ni * 8 + lcol * 2;
            if (row < R_ROWS)
                *(float2*)&Cb[(size_t)row * T_LEN + col] =
                    make_float2(acc[mi][ni][0], acc[mi][ni][1]);
            if (row + 8 < R_ROWS)
                *(float2*)&Cb[(size_t)(row + 8) * T_LEN + col] =
                    make_float2(acc[mi][ni][2], acc[mi][ni][3]);
        }
    }
}

// ============================================================
// SIMT slab GEMM (used for m2 only):
//   per bz: C[m,n] = sum_{h<64} A[m, z*64+h] * B[n, z*64+h]
// ============================================================
__global__ void __launch_bounds__(256) slab_gemm_kernel(
    const float* __restrict__ A, long sAb, long sAz,
    const float* __restrict__ B, long sBb, long sBz,
    float* __restrict__ C, int ldC, int M, int N)
{
    const int bz = blockIdx.z;
    const int b = bz / NH, z = bz % NH;
    const float* Ab = A + (size_t)b * sAb + (size_t)z * sAz;
    const float* Bb = B + (size_t)b * sBb + (size_t)z * sBz;
    float* Cb = C + (size_t)bz * M * ldC;

    __shared__ float Qs[64][68];
    __shared__ float Ks[64][68];

    const int tid = threadIdx.x;
    const int mbase = blockIdx.y * 64, nbase = blockIdx.x * 64;

#pragma unroll
    for (int i = 0; i < 4; i++) {
        int fl = tid + 256 * i;
        int row = fl >> 4;
        int hc = (fl & 15) * 4;
        float4 v = make_float4(0.f, 0.f, 0.f, 0.f);
        if (mbase + row < M)
            v = *(const float4*)&Ab[(size_t)(mbase + row) * D_MODEL + hc];
        Qs[hc + 0][row] = v.x; Qs[hc + 1][row] = v.y;
        Qs[hc + 2][row] = v.z; Qs[hc + 3][row] = v.w;
    }
#pragma unroll
    for (int i = 0; i < 4; i++) {
        int fl = tid + 256 * i;
        int row = fl >> 4;
        int hc = (fl & 15) * 4;
        float4 v = make_float4(0.f, 0.f, 0.f, 0.f);
        if (nbase + row < N)
            v = *(const float4*)&Bb[(size_t)(nbase + row) * D_MODEL + hc];
        Ks[hc + 0][row] = v.x; Ks[hc + 1][row] = v.y;
        Ks[hc + 2][row] = v.z; Ks[hc + 3][row] = v.w;
    }
    __syncthreads();

    const int tx = tid & 15, ty = tid >> 4;
    float acc[4][4];
#pragma unroll
    for (int i = 0; i < 4; i++)
#pragma unroll
        for (int j = 0; j < 4; j++) acc[i][j] = 0.f;

#pragma unroll
    for (int h = 0; h < 64; h++) {
        float ar[4], br[4];
        *(float4*)&ar[0] = *(float4*)&Qs[h][ty * 4];
        *(float4*)&br[0] = *(float4*)&Ks[h][tx * 4];
#pragma unroll
        for (int i = 0; i < 4; i++)
#pragma unroll
            for (int j = 0; j < 4; j++)
                acc[i][j] = fmaf(ar[i], br[j], acc[i][j]);
    }

#pragma unroll
    for (int i = 0; i < 4; i++) {
        int m = mbase + ty * 4 + i;
        if (m < M) {
#pragma unroll
            for (int j = 0; j < 4; j++) {
                int n = nbase + tx * 4 + j;
                if (n < N) Cb[(size_t)m * ldC + n] = acc[i][j];
            }
        }
    }
}

// ============================================================
// Softmax over t for 4 synonym rows, combine into mean weights
// ============================================================
__global__ void __launch_bounds__(128) softmax_combine_kernel(
    const float* __restrict__ scores, float* __restrict__ w)
{
    __shared__ float ex[4][1024];
    __shared__ float invl[4];
    const int blk = blockIdx.x;          // bz*50 + c
    const int bz = blk / C_CLS, c = blk % C_CLS;
    const int warp = threadIdx.x >> 5, lane = threadIdx.x & 31;

    const float* row = scores + ((size_t)bz * R_ROWS + c * 4 + warp) * T_LEN;

    float m = -INFINITY;
    for (int t = lane; t < T_LEN; t += 32) m = fmaxf(m, row[t]);
#pragma unroll
    for (int o = 16; o > 0; o >>= 1) m = fmaxf(m, __shfl_xor_sync(0xffffffffu, m, o));

    float ssum = 0.f;
    for (int t = lane; t < T_LEN; t += 32) {
        float e = expf(row[t] - m);
        ex[warp][t] = e;
        ssum += e;
    }
#pragma unroll
    for (int o = 16; o > 0; o >>= 1) ssum += __shfl_xor_sync(0xffffffffu, ssum, o);
    if (lane == 0) invl[warp] = 0.25f / ssum;
    __syncthreads();

    float* wr = w + ((size_t)bz * C_CLS + c) * T_LEN;
    for (int t = threadIdx.x; t < T_LEN; t += 128)
        wr[t] = ex[0][t] * invl[0] + ex[1][t] * invl[1]
              + ex[2][t] * invl[2] + ex[3][t] * invl[3];
}

// ============================================================
// tanh elementwise (Kh = tanh(H)), float4 vectorized
// ============================================================
__global__ void __launch_bounds__(256) tanh_kernel(
    const float* __restrict__ in, float* __restrict__ outp, int n4)
{
    int i = blockIdx.x * blockDim.x + threadIdx.x;
    if (i < n4) {
        float4 v = ((const float4*)in)[i];
        v.x = tanhf(v.x); v.y = tanhf(v.y);
        v.z = tanhf(v.z); v.w = tanhf(v.w);
        ((float4*)outp)[i] = v;
    }
}

// ============================================================
// Final: out[b,c] = sum_{z,t} w[bz,c,t] * m2[bz,t,c]
// ============================================================
__global__ void __launch_bounds__(256) final_out_kernel(
    const float* __restrict__ w, const float* __restrict__ m2,
    float* __restrict__ out)
{
    const int blk = blockIdx.x;           // b*50 + c
    const int b = blk / C_CLS, c = blk % C_CLS;
    float acc = 0.f;
    for (int idx = threadIdx.x; idx < NH * T_LEN; idx += 256) {
        int z = idx >> 10, t = idx & 1023;
        int bz = b * NH + z;
        float wv = w [((size_t)bz * C_CLS + c) * T_LEN + t];
        float mv = m2[((size_t)bz * T_LEN + t) * C_CLS + c];
        acc += wv * mv;
    }
    __shared__ float red[256];
    red[threadIdx.x] = acc;
    __syncthreads();
    for (int s = 128; s > 0; s >>= 1) {
        if (threadIdx.x < s) red[threadIdx.x] += red[threadIdx.x + s];
        __syncthreads();
    }
    if (threadIdx.x == 0) out[blk] = red[0];
}

// ============================================================
extern "C" void kernel_launch(void* const* d_in, const int* in_sizes, int n_in,
                              void* d_out, int out_size)
{
    const float* Q   = (const float*)d_in[0];
    const float* H   = (const float*)d_in[1];
    const float* ql  = (const float*)d_in[2];
    const float* WQw = (const float*)d_in[3];
    const float* WQb = (const float*)d_in[4];
    const float* WKw = (const float*)d_in[5];
    const float* WKb = (const float*)d_in[6];
    const float* WVw = (const float*)d_in[7];
    const float* WVb = (const float*)d_in[8];
    float* out = (float*)d_out;

    float *qproj, *kproj, *ktanh, *wql, *scores, *w, *m2;
    cudaGetSymbolAddress((void**)&qproj,  g_qproj);
    cudaGetSymbolAddress((void**)&kproj,  g_kproj);
    cudaGetSymbolAddress((void**)&ktanh,  g_ktanh);
    cudaGetSymbolAddress((void**)&wql,    g_wql);
    cudaGetSymbolAddress((void**)&scores, g_scores);
    cudaGetSymbolAddress((void**)&w,      g_w);
    cudaGetSymbolAddress((void**)&m2,     g_m2);

    // allow large dynamic smem (host-side attribute, idempotent)
    cudaFuncSetAttribute(gemm_tf32_kernel<0>,
                         cudaFuncAttributeMaxDynamicSharedMemorySize, GEMM_SMEM);
    cudaFuncSetAttribute(gemm_tf32_kernel<1>,
                         cudaFuncAttributeMaxDynamicSharedMemorySize, GEMM_SMEM);
    cudaFuncSetAttribute(scores_tf32_kernel,
                         cudaFuncAttributeMaxDynamicSharedMemorySize, SC_SMEM);

    // projections on tensor cores (3xTF32, fp32-accurate)
    gemm_tf32_kernel<0><<<dim3(6, 2),  256, GEMM_SMEM>>>(Q,  WQw, WQb, qproj, R_ROWS, D_MODEL, D_MODEL);
    gemm_tf32_kernel<1><<<dim3(6, 32), 256, GEMM_SMEM>>>(H,  WKw, WKb, kproj, B_BATCH * T_LEN, D_MODEL, D_MODEL);
    gemm_tf32_kernel<0><<<dim3(6, 1),  256, GEMM_SMEM>>>(ql, WVw, WVb, wql,   C_CLS,  D_MODEL, D_MODEL);
    tanh_kernel<<<(B_BATCH * T_LEN * D_MODEL / 4 + 255) / 256, 256>>>(H, ktanh, B_BATCH * T_LEN * D_MODEL / 4);

    // scores[bz][r=200][t=1024] on tensor cores
    scores_tf32_kernel<<<dim3(8, 4, BZ), 256, SC_SMEM>>>(qproj, kproj, scores);

    // softmax over t + combine synonyms into mean weights
    softmax_combine_kernel<<<BZ * C_CLS, 128>>>(scores, w);

    // m2[bz][t=1024][c=50] = ktanh . wql  (over 64-wide head slice)
    slab_gemm_kernel<<<dim3(1, 16, BZ), 256>>>(
        ktanh, (long)T_LEN * D_MODEL, (long)HDIM,
        wql, 0L, (long)HDIM,
        m2, C_CLS, T_LEN, C_CLS);

    // out[b,c] = sum_{z,t} w * m2
    final_out_kernel<<<B_BATCH * C_CLS, 256>>>(w, m2, out);
}

// round 10
// speedup vs baseline: 2.3546x; 2.3546x over previous
#include <cuda_runtime.h>
#include <cuda_fp16.h>
#include <math.h>
#include <stdint.h>

// Problem dims (fixed)
#define D_MODEL 768
#define NH      12
#define HDIM    64
#define C_CLS   50
#define B_BATCH 4
#define T_LEN   1024
#define R_ROWS  200
#define BZ      48

// -------- fp32 scratch (explicitly aligned for vector access) --------
__device__ __align__(256) float g_wql[C_CLS * D_MODEL];
__device__ __align__(256) float g_scores[BZ * R_ROWS * T_LEN];
__device__ __align__(256) float g_w[BZ * C_CLS * T_LEN];

// -------- fp16 hi/lo split pool (offsets in halves; all 16B-multiples) --------
#define AH_H   0L
#define AH_L   3145728L
#define WKT_H  6291456L
#define WQT_H  7471104L
#define WVT_H  8650752L
#define W_PL   589824L
#define QH_    9830400L
#define QL_    9984000L
#define QLH_   10137600L
#define QLL_   10176000L
#define KPH_   10214400L
#define KPL_   13360128L
#define QPH_   16505856L
#define QPL_   16659456L
#define POOL_SZ 16813056L
__device__ __align__(256) __half g_hf[POOL_SZ];

// ============================================================
// helpers
// ============================================================
__device__ __forceinline__ void split2h(float v, __half& h, __half& l) {
    h = __float2half_rn(v);
    l = __float2half_rn(v - __half2float(h));
}

__device__ __forceinline__ void mma_f16(float* c, const uint32_t* a, const uint32_t* b) {
    asm volatile(
        "mma.sync.aligned.m16n8k16.row.col.f32.f16.f16.f32 "
        "{%0,%1,%2,%3}, {%4,%5,%6,%7}, {%8,%9}, {%0,%1,%2,%3};"
        : "+f"(c[0]), "+f"(c[1]), "+f"(c[2]), "+f"(c[3])
        : "r"(a[0]), "r"(a[1]), "r"(a[2]), "r"(a[3]), "r"(b[0]), "r"(b[1]));
}

// ============================================================
// zero output (out is poisoned; we accumulate with atomics)
// ============================================================
__global__ void zero_out_kernel(float* out) {
    if (threadIdx.x < B_BATCH * C_CLS) out[threadIdx.x] = 0.f;
}

// ============================================================
// fp32 -> (hi, lo) fp16 planes, elementwise
// ============================================================
__global__ void __launch_bounds__(256) split_rows_kernel(
    const float* __restrict__ x, __half* __restrict__ oh,
    __half* __restrict__ ol, int n)
{
    int i = blockIdx.x * blockDim.x + threadIdx.x;
    if (i < n) {
        __half h, l;
        split2h(x[i], h, l);
        oh[i] = h; ol[i] = l;
    }
}

// W[k][n] fp32 -> Wt hi/lo [n][k] fp16 (z selects WK/WQ/WV)
__global__ void __launch_bounds__(256) split_transpose_kernel(
    const float* __restrict__ W0, const float* __restrict__ W1,
    const float* __restrict__ W2, __half* __restrict__ pool)
{
    __shared__ float t[32][33];
    const float* W = (blockIdx.z == 0) ? W0 : (blockIdx.z == 1) ? W1 : W2;
    const long oh = (blockIdx.z == 0) ? WKT_H : (blockIdx.z == 1) ? WQT_H : WVT_H;
    const long ol = oh + W_PL;
    const int k0 = blockIdx.y * 32, n0 = blockIdx.x * 32;
    const int tx = threadIdx.x & 31, ty = threadIdx.x >> 5;
#pragma unroll
    for (int j = 0; j < 32; j += 8)
        t[ty + j][tx] = W[(size_t)(k0 + ty + j) * D_MODEL + n0 + tx];
    __syncthreads();
#pragma unroll
    for (int j = 0; j < 32; j += 8) {
        float v = t[tx][ty + j];
        __half h, l;
        split2h(v, h, l);
        size_t idx = (size_t)(n0 + ty + j) * D_MODEL + k0 + tx;
        pool[oh + idx] = h; pool[ol + idx] = l;
    }
}

// ============================================================
// Fused projection GEMM (fp16x3 = ~fp32 accuracy):
//  z=0: kproj = tanh(H@WK+b)  -> fp16 hi/lo planes   (M=4096)
//  z=1: qproj = Q@WQ+b        -> fp16 hi/lo planes   (M=200)
//  z=2: wql   = ql@WV+b       -> fp32                (M=50)
// Block 128x128, BK=32, 256 thr = 8 warps (4x2), warp tile 32x64.
// ============================================================
#define PSTR 40   // halves per smem row (32 padded; 80B stride = 16B multiple)

__global__ void __launch_bounds__(256) proj_f16_kernel(
    const __half* __restrict__ pool, __half* __restrict__ poolw,
    const float* __restrict__ WKb, const float* __restrict__ WQb,
    const float* __restrict__ WVb, float* __restrict__ wqlout)
{
    const int z = blockIdx.z;
    int M; const __half *Ah, *Al, *Bh, *Bl; const float* bias;
    if (z == 0) {
        M = 4096; Ah = pool + AH_H; Al = pool + AH_L;
        Bh = pool + WKT_H; Bl = pool + WKT_H + W_PL; bias = WKb;
    } else if (z == 1) {
        if (blockIdx.y >= 2) return;
        M = R_ROWS; Ah = pool + QH_; Al = pool + QL_;
        Bh = pool + WQT_H; Bl = pool + WQT_H + W_PL; bias = WQb;
    } else {
        if (blockIdx.y >= 1) return;
        M = C_CLS; Ah = pool + QLH_; Al = pool + QLL_;
        Bh = pool + WVT_H; Bl = pool + WVT_H + W_PL; bias = WVb;
    }

    __shared__ __half Ahs[128 * PSTR], Als[128 * PSTR];
    __shared__ __half Bhs[128 * PSTR], Bls[128 * PSTR];

    const int tid = threadIdx.x;
    const int warp = tid >> 5, lane = tid & 31;
    const int wm = (warp >> 1) * 32, wn = (warp & 1) * 64;
    const int bm = blockIdx.y * 128, bn = blockIdx.x * 128;
    const int lrow = lane >> 2, lcol = lane & 3;

    float acc[2][8][4];
#pragma unroll
    for (int mi = 0; mi < 2; mi++)
#pragma unroll
        for (int ni = 0; ni < 8; ni++)
#pragma unroll
            for (int q = 0; q < 4; q++) acc[mi][ni][q] = 0.f;

    const uint4 z4 = make_uint4(0u, 0u, 0u, 0u);
    uint4 pah[2], pal[2], pbh[2], pbl[2];
#pragma unroll
    for (int i = 0; i < 2; i++) {
        int fl = tid + 256 * i, row = fl >> 2, ch = fl & 3;
        bool ok = (bm + row) < M;
        size_t ka = (size_t)(bm + row) * D_MODEL + ch * 8;
        size_t kb = (size_t)(bn + row) * D_MODEL + ch * 8;
        pah[i] = ok ? *(const uint4*)&Ah[ka] : z4;
        pal[i] = ok ? *(const uint4*)&Al[ka] : z4;
        pbh[i] = *(const uint4*)&Bh[kb];
        pbl[i] = *(const uint4*)&Bl[kb];
    }

    for (int k0 = 0; k0 < D_MODEL; k0 += 32) {
#pragma unroll
        for (int i = 0; i < 2; i++) {
            int fl = tid + 256 * i, row = fl >> 2, ch = fl & 3;
            *(uint4*)&Ahs[row * PSTR + ch * 8] = pah[i];
            *(uint4*)&Als[row * PSTR + ch * 8] = pal[i];
            *(uint4*)&Bhs[row * PSTR + ch * 8] = pbh[i];
            *(uint4*)&Bls[row * PSTR + ch * 8] = pbl[i];
        }
        __syncthreads();
        if (k0 + 32 < D_MODEL) {
#pragma unroll
            for (int i = 0; i < 2; i++) {
                int fl = tid + 256 * i, row = fl >> 2, ch = fl & 3;
                bool ok = (bm + row) < M;
                size_t ka = (size_t)(bm + row) * D_MODEL + k0 + 32 + ch * 8;
                size_t kb = (size_t)(bn + row) * D_MODEL + k0 + 32 + ch * 8;
                pah[i] = ok ? *(const uint4*)&Ah[ka] : z4;
                pal[i] = ok ? *(const uint4*)&Al[ka] : z4;
                pbh[i] = *(const uint4*)&Bh[kb];
                pbl[i] = *(const uint4*)&Bl[kb];
            }
        }
#pragma unroll
        for (int ck = 0; ck < 2; ck++) {
            const int kk = ck * 16 + lcol * 2;
            uint32_t ah[2][4], al_[2][4];
#pragma unroll
            for (int mi = 0; mi < 2; mi++) {
                const int r0 = wm + mi * 16 + lrow;
                ah[mi][0]  = *(const uint32_t*)&Ahs[r0 * PSTR + kk];
                ah[mi][1]  = *(const uint32_t*)&Ahs[(r0 + 8) * PSTR + kk];
                ah[mi][2]  = *(const uint32_t*)&Ahs[r0 * PSTR + kk + 8];
                ah[mi][3]  = *(const uint32_t*)&Ahs[(r0 + 8) * PSTR + kk + 8];
                al_[mi][0] = *(const uint32_t*)&Als[r0 * PSTR + kk];
                al_[mi][1] = *(const uint32_t*)&Als[(r0 + 8) * PSTR + kk];
                al_[mi][2] = *(const uint32_t*)&Als[r0 * PSTR + kk + 8];
                al_[mi][3] = *(const uint32_t*)&Als[(r0 + 8) * PSTR + kk + 8];
            }
            uint32_t bh[8][2], bl_[8][2];
#pragma unroll
            for (int ni = 0; ni < 8; ni++) {
                const int rb = wn + ni * 8 + lrow;
                bh[ni][0]  = *(const uint32_t*)&Bhs[rb * PSTR + kk];
                bh[ni][1]  = *(const uint32_t*)&Bhs[rb * PSTR + kk + 8];
                bl_[ni][0] = *(const uint32_t*)&Bls[rb * PSTR + kk];
                bl_[ni][1] = *(const uint32_t*)&Bls[rb * PSTR + kk + 8];
            }
#pragma unroll
            for (int ni = 0; ni < 8; ni++)
#pragma unroll
                for (int mi = 0; mi < 2; mi++)
                    mma_f16(acc[mi][ni], ah[mi], bh[ni]);
#pragma unroll
            for (int ni = 0; ni < 8; ni++)
#pragma unroll
                for (int mi = 0; mi < 2; mi++)
                    mma_f16(acc[mi][ni], ah[mi], bl_[ni]);
#pragma unroll
            for (int ni = 0; ni < 8; ni++)
#pragma unroll
                for (int mi = 0; mi < 2; mi++)
                    mma_f16(acc[mi][ni], al_[mi], bh[ni]);
        }
        __syncthreads();
    }

    // epilogue
    const long oh = (z == 0) ? KPH_ : QPH_;
    const long ol = (z == 0) ? KPL_ : QPL_;
#pragma unroll
    for (int mi = 0; mi < 2; mi++) {
        const int row = bm + wm + mi * 16 + lrow;
#pragma unroll
        for (int ni = 0; ni < 8; ni++) {
            const int col = bn + wn + ni * 8 + lcol * 2;
            const float b0 = bias[col], b1 = bias[col + 1];
            float v0 = acc[mi][ni][0] + b0, v1 = acc[mi][ni][1] + b1;
            float v2 = acc[mi][ni][2] + b0, v3 = acc[mi][ni][3] + b1;
            if (z == 0) {
                v0 = tanhf(v0); v1 = tanhf(v1);
                v2 = tanhf(v2); v3 = tanhf(v3);
            }
            if (z <= 1) {
                if (row < M) {
                    __half h0, l0, h1, l1;
                    split2h(v0, h0, l0); split2h(v1, h1, l1);
                    *(__half2*)&poolw[oh + (size_t)row * D_MODEL + col] = __halves2half2(h0, h1);
                    *(__half2*)&poolw[ol + (size_t)row * D_MODEL + col] = __halves2half2(l0, l1);
                }
                if (row + 8 < M) {
                    __half h2, l2, h3, l3;
                    split2h(v2, h2, l2); split2h(v3, h3, l3);
                    *(__half2*)&poolw[oh + (size_t)(row + 8) * D_MODEL + col] = __halves2half2(h2, h3);
                    *(__half2*)&poolw[ol + (size_t)(row + 8) * D_MODEL + col] = __halves2half2(l2, l3);
                }
            } else {
                if (row < M)
                    *(float2*)&wqlout[(size_t)row * D_MODEL + col] = make_float2(v0, v1);
                if (row + 8 < M)
                    *(float2*)&wqlout[(size_t)(row + 8) * D_MODEL + col] = make_float2(v2, v3);
            }
        }
    }
}

// ============================================================
// Scores GEMM (fp16x3): per bz: C[m,t] = qproj . kproj over 64-k slice
// Block 64x128, K=64 single pass, 8 warps (2x4), warp tile 32x32.
// ============================================================
#define SSTRH 72
#define SC_SMEM_B ((64 * SSTRH * 2 + 128 * SSTRH * 2) * 2)   // 55296

__global__ void __launch_bounds__(256) scores_f16_kernel(
    const __half* __restrict__ pool, float* __restrict__ scores)
{
    extern __shared__ __align__(16) __half ssm[];
    __half* Ahs = ssm;
    __half* Als = Ahs + 64 * SSTRH;
    __half* Bhs = Als + 64 * SSTRH;
    __half* Bls = Bhs + 128 * SSTRH;

    const int bz = blockIdx.z, b = bz / NH, zz = bz % NH;
    const __half* Aph = pool + QPH_ + zz * HDIM;
    const __half* Apl = pool + QPL_ + zz * HDIM;
    const __half* Bph = pool + KPH_ + (size_t)b * T_LEN * D_MODEL + zz * HDIM;
    const __half* Bpl = pool + KPL_ + (size_t)b * T_LEN * D_MODEL + zz * HDIM;
    float* Cb = scores + (size_t)bz * R_ROWS * T_LEN;

    const int tid = threadIdx.x;
    const int warp = tid >> 5, lane = tid & 31;
    const int wm = (warp >> 2) * 32, wn = (warp & 3) * 32;
    const int mbase = blockIdx.y * 64, nbase = blockIdx.x * 128;
    const int lrow = lane >> 2, lcol = lane & 3;
    const uint4 z4 = make_uint4(0u, 0u, 0u, 0u);

#pragma unroll
    for (int i = 0; i < 2; i++) {
        int fl = tid + 256 * i, row = fl >> 3, ch = fl & 7;
        bool ok = (mbase + row) < R_ROWS;
        size_t ga = (size_t)(mbase + row) * D_MODEL + ch * 8;
        *(uint4*)&Ahs[row * SSTRH + ch * 8] = ok ? *(const uint4*)&Aph[ga] : z4;
        *(uint4*)&Als[row * SSTRH + ch * 8] = ok ? *(const uint4*)&Apl[ga] : z4;
    }
#pragma unroll
    for (int i = 0; i < 4; i++) {
        int fl = tid + 256 * i, row = fl >> 3, ch = fl & 7;
        size_t gb = (size_t)(nbase + row) * D_MODEL + ch * 8;
        *(uint4*)&Bhs[row * SSTRH + ch * 8] = *(const uint4*)&Bph[gb];
        *(uint4*)&Bls[row * SSTRH + ch * 8] = *(const uint4*)&Bpl[gb];
    }
    __syncthreads();

    float acc[2][4][4];
#pragma unroll
    for (int mi = 0; mi < 2; mi++)
#pragma unroll
        for (int ni = 0; ni < 4; ni++)
#pragma unroll
            for (int q = 0; q < 4; q++) acc[mi][ni][q] = 0.f;

#pragma unroll
    for (int ck = 0; ck < 4; ck++) {
        const int kk = ck * 16 + lcol * 2;
        uint32_t ah[2][4], al_[2][4];
#pragma unroll
        for (int mi = 0; mi < 2; mi++) {
            const int r0 = wm + mi * 16 + lrow;
            ah[mi][0]  = *(const uint32_t*)&Ahs[r0 * SSTRH + kk];
            ah[mi][1]  = *(const uint32_t*)&Ahs[(r0 + 8) * SSTRH + kk];
            ah[mi][2]  = *(const uint32_t*)&Ahs[r0 * SSTRH + kk + 8];
            ah[mi][3]  = *(const uint32_t*)&Ahs[(r0 + 8) * SSTRH + kk + 8];
            al_[mi][0] = *(const uint32_t*)&Als[r0 * SSTRH + kk];
            al_[mi][1] = *(const uint32_t*)&Als[(r0 + 8) * SSTRH + kk];
            al_[mi][2] = *(const uint32_t*)&Als[r0 * SSTRH + kk + 8];
            al_[mi][3] = *(const uint32_t*)&Als[(r0 + 8) * SSTRH + kk + 8];
        }
        uint32_t bh[4][2], bl_[4][2];
#pragma unroll
        for (int ni = 0; ni < 4; ni++) {
            const int rb = wn + ni * 8 + lrow;
            bh[ni][0]  = *(const uint32_t*)&Bhs[rb * SSTRH + kk];
            bh[ni][1]  = *(const uint32_t*)&Bhs[rb * SSTRH + kk + 8];
            bl_[ni][0] = *(const uint32_t*)&Bls[rb * SSTRH + kk];
            bl_[ni][1] = *(const uint32_t*)&Bls[rb * SSTRH + kk + 8];
        }
#pragma unroll
        for (int ni = 0; ni < 4; ni++)
#pragma unroll
            for (int mi = 0; mi < 2; mi++)
                mma_f16(acc[mi][ni], ah[mi], bh[ni]);
#pragma unroll
        for (int ni = 0; ni < 4; ni++)
#pragma unroll
            for (int mi = 0; mi < 2; mi++)
                mma_f16(acc[mi][ni], ah[mi], bl_[ni]);
#pragma unroll
        for (int ni = 0; ni < 4; ni++)
#pragma unroll
            for (int mi = 0; mi < 2; mi++)
                mma_f16(acc[mi][ni], al_[mi], bh[ni]);
    }

#pragma unroll
    for (int mi = 0; mi < 2; mi++) {
        const int row = mbase + wm + mi * 16 + lrow;
#pragma unroll
        for (int ni = 0; ni < 4; ni++) {
            const int col = nbase + wn + ni * 8 + lcol * 2;
            if (row < R_ROWS)
                *(float2*)&Cb[(size_t)row * T_LEN + col] =
                    make_float2(acc[mi][ni][0], acc[mi][ni][1]);
            if (row + 8 < R_ROWS)
                *(float2*)&Cb[(size_t)(row + 8) * T_LEN + col] =
                    make_float2(acc[mi][ni][2], acc[mi][ni][3]);
        }
    }
}

// ============================================================
// Softmax over t for 4 synonym rows -> combined mean weights
// ============================================================
__global__ void __launch_bounds__(128) softmax_combine_kernel(
    const float* __restrict__ scores, float* __restrict__ w)
{
    __shared__ float ex[4][1024];
    __shared__ float invl[4];
    const int blk = blockIdx.x;
    const int bz = blk / C_CLS, c = blk % C_CLS;
    const int warp = threadIdx.x >> 5, lane = threadIdx.x & 31;

    const float* row = scores + ((size_t)bz * R_ROWS + c * 4 + warp) * T_LEN;

    float m = -INFINITY;
    for (int t = lane; t < T_LEN; t += 32) m = fmaxf(m, row[t]);
#pragma unroll
    for (int o = 16; o > 0; o >>= 1) m = fmaxf(m, __shfl_xor_sync(0xffffffffu, m, o));

    float ssum = 0.f;
    for (int t = lane; t < T_LEN; t += 32) {
        float e = expf(row[t] - m);
        ex[warp][t] = e;
        ssum += e;
    }
#pragma unroll
    for (int o = 16; o > 0; o >>= 1) ssum += __shfl_xor_sync(0xffffffffu, ssum, o);
    if (lane == 0) invl[warp] = 0.25f / ssum;
    __syncthreads();

    float* wr = w + ((size_t)bz * C_CLS + c) * T_LEN;
    for (int t = threadIdx.x; t < T_LEN; t += 128)
        wr[t] = ex[0][t] * invl[0] + ex[1][t] * invl[1]
              + ex[2][t] * invl[2] + ex[3][t] * invl[3];
}

// ============================================================
// Fused m2 + final:  per bz, t-tile:
//   m2[t,c] = sum_h tanh(H[b,t,z*64+h]) * wql[c,z*64+h]
//   out[b,c] += sum_t w[bz,c,t] * m2[t,c]     (atomicAdd)
// NOTE: smem padded to 68 (272B row stride, 16B multiple) — the 65-pad
// variant made every odd-h float4 LDS misaligned (the round-8/9 trap).
// ============================================================
__global__ void __launch_bounds__(256) m2_fused_kernel(
    const float* __restrict__ H, const float* __restrict__ wql,
    const float* __restrict__ w, float* __restrict__ out)
{
    const int bz = blockIdx.z;
    const int b = bz / NH, z = bz % NH;
    const int tbase = blockIdx.y * 64;

    __shared__ float Qs[64][68];   // [h][t-local] = tanh(H)
    __shared__ float Ks[64][68];   // [h][c]       = wql

    const int tid = threadIdx.x;

#pragma unroll
    for (int i = 0; i < 4; i++) {
        int fl = tid + 256 * i;
        int row = fl >> 4;            // t-local 0..63
        int hc = (fl & 15) * 4;
        float4 v = *(const float4*)&H[(size_t)(b * T_LEN + tbase + row) * D_MODEL + z * HDIM + hc];
        Qs[hc + 0][row] = tanhf(v.x); Qs[hc + 1][row] = tanhf(v.y);
        Qs[hc + 2][row] = tanhf(v.z); Qs[hc + 3][row] = tanhf(v.w);
    }
#pragma unroll
    for (int i = 0; i < 4; i++) {
        int fl = tid + 256 * i;
        int row = fl >> 4;            // c 0..63
        int hc = (fl & 15) * 4;
        float4 v = make_float4(0.f, 0.f, 0.f, 0.f);
        if (row < C_CLS)
            v = *(const float4*)&wql[(size_t)row * D_MODEL + z * HDIM + hc];
        Ks[hc + 0][row] = v.x; Ks[hc + 1][row] = v.y;
        Ks[hc + 2][row] = v.z; Ks[hc + 3][row] = v.w;
    }
    __syncthreads();

    const int tx = tid & 15, ty = tid >> 4;
    float acc[4][4];
#pragma unroll
    for (int i = 0; i < 4; i++)
#pragma unroll
        for (int j = 0; j < 4; j++) acc[i][j] = 0.f;

#pragma unroll
    for (int h = 0; h < 64; h++) {
        float ar[4], br[4];
        *(float4*)&ar[0] = *(float4*)&Qs[h][ty * 4];
        *(float4*)&br[0] = *(float4*)&Ks[h][tx * 4];
#pragma unroll
        for (int i = 0; i < 4; i++)
#pragma unroll
            for (int j = 0; j < 4; j++)
                acc[i][j] = fmaf(ar[i], br[j], acc[i][j]);
    }
    __syncthreads();   // Qs region about to be reused for partials

    // weight by w[bz,c,t] and reduce over this block's 64 t's
    float* pm = &Qs[0][0];             // [16][64] partials
    float p[4];
#pragma unroll
    for (int j = 0; j < 4; j++) {
        const int c = tx * 4 + j;
        p[j] = 0.f;
        if (c < C_CLS) {
            float4 wv = *(const float4*)&w[((size_t)bz * C_CLS + c) * T_LEN + tbase + ty * 4];
            p[j] = acc[0][j] * wv.x + acc[1][j] * wv.y
                 + acc[2][j] * wv.z + acc[3][j] * wv.w;
        }
        pm[ty * 64 + tx * 4 + j] = p[j];
    }
    __syncthreads();

    if (tid < 64 && tid < C_CLS) {
        float s = 0.f;
#pragma unroll
        for (int r = 0; r < 16; r++) s += pm[r * 64 + tid];
        atomicAdd(&out[b * C_CLS + tid], s);
    }
}

// ============================================================
extern "C" void kernel_launch(void* const* d_in, const int* in_sizes, int n_in,
                              void* d_out, int out_size)
{
    const float* Q   = (const float*)d_in[0];
    const float* H   = (const float*)d_in[1];
    const float* ql  = (const float*)d_in[2];
    const float* WQw = (const float*)d_in[3];
    const float* WQb = (const float*)d_in[4];
    const float* WKw = (const float*)d_in[5];
    const float* WKb = (const float*)d_in[6];
    const float* WVw = (const float*)d_in[7];
    const float* WVb = (const float*)d_in[8];
    float* out = (float*)d_out;

    __half* pool;
    float *wql, *scores, *w;
    cudaGetSymbolAddress((void**)&pool,   g_hf);
    cudaGetSymbolAddress((void**)&wql,    g_wql);
    cudaGetSymbolAddress((void**)&scores, g_scores);
    cudaGetSymbolAddress((void**)&w,      g_w);

    cudaFuncSetAttribute(scores_f16_kernel,
                         cudaFuncAttributeMaxDynamicSharedMemorySize, SC_SMEM_B);

    zero_out_kernel<<<1, 256>>>(out);

    // pre-split fp32 -> fp16 hi/lo
    split_rows_kernel<<<(B_BATCH * T_LEN * D_MODEL + 255) / 256, 256>>>(
        H, pool + AH_H, pool + AH_L, B_BATCH * T_LEN * D_MODEL);
    split_rows_kernel<<<(R_ROWS * D_MODEL + 255) / 256, 256>>>(
        Q, pool + QH_, pool + QL_, R_ROWS * D_MODEL);
    split_rows_kernel<<<(C_CLS * D_MODEL + 255) / 256, 256>>>(
        ql, pool + QLH_, pool + QLL_, C_CLS * D_MODEL);
    split_transpose_kernel<<<dim3(24, 24, 3), 256>>>(WKw, WQw, WVw, pool);

    // fused projections (kproj+tanh+split, qproj+split, wql fp32)
    proj_f16_kernel<<<dim3(6, 32, 3), 256>>>(pool, pool, WKb, WQb, WVb, wql);

    // scores per (b,z) on fp16x3 mma
    scores_f16_kernel<<<dim3(8, 4, BZ), 256, SC_SMEM_B>>>(pool, scores);

    // softmax + synonym-mean combine
    softmax_combine_kernel<<<BZ * C_CLS, 128>>>(scores, w);

    // fused m2 + weighted reduce into out
    m2_fused_kernel<<<dim3(1, 16, BZ), 256>>>(H, wql, w, out);
}

// round 11
// speedup vs baseline: 2.5880x; 1.0991x over previous
#include <cuda_runtime.h>
#include <cuda_fp16.h>
#include <math.h>
#include <stdint.h>

// Problem dims (fixed)
#define D_MODEL 768
#define NH      12
#define HDIM    64
#define C_CLS   50
#define B_BATCH 4
#define T_LEN   1024
#define R_ROWS  200
#define BZ      48

// -------- fp32 scratch (explicitly aligned for vector access) --------
__device__ __align__(256) float g_wql[C_CLS * D_MODEL];
__device__ __align__(256) float g_scores[BZ * R_ROWS * T_LEN];
__device__ __align__(256) float g_w[BZ * C_CLS * T_LEN];

// -------- fp16 hi/lo split pool (offsets in halves; all 16B-multiples) --------
#define AH_H   0L
#define AH_L   3145728L
#define WKT_H  6291456L
#define WQT_H  7471104L
#define WVT_H  8650752L
#define W_PL   589824L
#define QH_    9830400L
#define QL_    9984000L
#define QLH_   10137600L
#define QLL_   10176000L
#define KPH_   10214400L
#define KPL_   13360128L
#define QPH_   16505856L
#define QPL_   16659456L
#define POOL_SZ 16813056L
__device__ __align__(256) __half g_hf[POOL_SZ];

// ============================================================
// helpers
// ============================================================
__device__ __forceinline__ void split2h(float v, __half& h, __half& l) {
    h = __float2half_rn(v);
    l = __float2half_rn(v - __half2float(h));
}

__device__ __forceinline__ void mma_f16(float* c, const uint32_t* a, const uint32_t* b) {
    asm volatile(
        "mma.sync.aligned.m16n8k16.row.col.f32.f16.f16.f32 "
        "{%0,%1,%2,%3}, {%4,%5,%6,%7}, {%8,%9}, {%0,%1,%2,%3};"
        : "+f"(c[0]), "+f"(c[1]), "+f"(c[2]), "+f"(c[3])
        : "r"(a[0]), "r"(a[1]), "r"(a[2]), "r"(a[3]), "r"(b[0]), "r"(b[1]));
}

__device__ __forceinline__ uint32_t smem_u32(const void* p) {
    uint32_t a;
    asm("{ .reg .u64 t; cvta.to.shared.u64 t, %1; cvt.u32.u64 %0, t; }"
        : "=r"(a) : "l"(p));
    return a;
}
__device__ __forceinline__ void cp_async16(uint32_t dst, const void* src) {
    asm volatile("cp.async.cg.shared.global [%0], [%1], 16;" :: "r"(dst), "l"(src));
}
#define CP_COMMIT() asm volatile("cp.async.commit_group;")
#define CP_WAIT1()  asm volatile("cp.async.wait_group 1;")

// ============================================================
// zero output (out is poisoned; we accumulate with atomics)
// ============================================================
__global__ void zero_out_kernel(float* out) {
    if (threadIdx.x < B_BATCH * C_CLS) out[threadIdx.x] = 0.f;
}

// ============================================================
// fp32 -> (hi, lo) fp16 planes, all three inputs in one launch
// ============================================================
#define N_H  (B_BATCH * T_LEN * D_MODEL)   // 3145728
#define N_Q  (R_ROWS * D_MODEL)            // 153600
#define N_QL (C_CLS * D_MODEL)             // 38400

__global__ void __launch_bounds__(256) split_all_kernel(
    const float* __restrict__ H, const float* __restrict__ Q,
    const float* __restrict__ ql, __half* __restrict__ pool)
{
    int i = blockIdx.x * blockDim.x + threadIdx.x;
    float v; long oh, ol; int idx;
    if (i < N_H) {
        v = H[i]; oh = AH_H; ol = AH_L; idx = i;
    } else if (i < N_H + N_Q) {
        idx = i - N_H; v = Q[idx]; oh = QH_; ol = QL_;
    } else if (i < N_H + N_Q + N_QL) {
        idx = i - N_H - N_Q; v = ql[idx]; oh = QLH_; ol = QLL_;
    } else return;
    __half h, l;
    split2h(v, h, l);
    pool[oh + idx] = h; pool[ol + idx] = l;
}

// W[k][n] fp32 -> Wt hi/lo [n][k] fp16 (z selects WK/WQ/WV)
__global__ void __launch_bounds__(256) split_transpose_kernel(
    const float* __restrict__ W0, const float* __restrict__ W1,
    const float* __restrict__ W2, __half* __restrict__ pool)
{
    __shared__ float t[32][33];
    const float* W = (blockIdx.z == 0) ? W0 : (blockIdx.z == 1) ? W1 : W2;
    const long oh = (blockIdx.z == 0) ? WKT_H : (blockIdx.z == 1) ? WQT_H : WVT_H;
    const long ol = oh + W_PL;
    const int k0 = blockIdx.y * 32, n0 = blockIdx.x * 32;
    const int tx = threadIdx.x & 31, ty = threadIdx.x >> 5;
#pragma unroll
    for (int j = 0; j < 32; j += 8)
        t[ty + j][tx] = W[(size_t)(k0 + ty + j) * D_MODEL + n0 + tx];
    __syncthreads();
#pragma unroll
    for (int j = 0; j < 32; j += 8) {
        float v = t[tx][ty + j];
        __half h, l;
        split2h(v, h, l);
        size_t idx = (size_t)(n0 + ty + j) * D_MODEL + k0 + tx;
        pool[oh + idx] = h; pool[ol + idx] = l;
    }
}

// ============================================================
// Fused projection GEMM (fp16x3, cp.async double-buffered):
//  z=0: kproj = tanh(H@WK+b)  -> fp16 hi/lo planes   (M=4096)
//  z=1: qproj = Q@WQ+b        -> fp16 hi/lo planes   (M=200)
//  z=2: wql   = ql@WV+b       -> fp32                (M=50)
// Block 128x128, BK=32, 256 thr = 8 warps (4x2), warp tile 32x64.
// Dynamic smem: 2 stages x 4 planes x 128x40 halves = 81920 B.
// OOB A-rows (z=1/2) read in-pool garbage; results row-guarded at store.
// ============================================================
#define PSTR 40                  // halves per smem row (80B = 16B multiple)
#define PLANE (128 * PSTR)       // halves per plane
#define PROJ_SMEM (2 * 4 * PLANE * 2)   // 81920 bytes
#define NITER 24                 // 768 / 32

__global__ void __launch_bounds__(256, 2) proj_f16_kernel(
    const __half* __restrict__ pool, __half* __restrict__ poolw,
    const float* __restrict__ WKb, const float* __restrict__ WQb,
    const float* __restrict__ WVb, float* __restrict__ wqlout)
{
    const int z = blockIdx.z;
    int M; const __half *Ah, *Al, *Bh, *Bl; const float* bias;
    if (z == 0) {
        M = 4096; Ah = pool + AH_H; Al = pool + AH_L;
        Bh = pool + WKT_H; Bl = pool + WKT_H + W_PL; bias = WKb;
    } else if (z == 1) {
        if (blockIdx.y >= 2) return;
        M = R_ROWS; Ah = pool + QH_; Al = pool + QL_;
        Bh = pool + WQT_H; Bl = pool + WQT_H + W_PL; bias = WQb;
    } else {
        if (blockIdx.y >= 1) return;
        M = C_CLS; Ah = pool + QLH_; Al = pool + QLL_;
        Bh = pool + WVT_H; Bl = pool + WVT_H + W_PL; bias = WVb;
    }

    extern __shared__ __align__(16) __half psm[];
    const uint32_t sbase = smem_u32(psm);

    const int tid = threadIdx.x;
    const int warp = tid >> 5, lane = tid & 31;
    const int wm = (warp >> 1) * 32, wn = (warp & 1) * 64;
    const int bm = blockIdx.y * 128, bn = blockIdx.x * 128;
    const int lrow = lane >> 2, lcol = lane & 3;

    const int crow = tid >> 2, cch = (tid & 3) * 8;  // copy indices (row, halves)

    // issue one stage's 4 plane tiles via cp.async (each thread: 8 x 16B)
    const __half* srcs[4] = { Ah, Al, Bh, Bl };
    auto issue = [&](int stage, int k0) {
#pragma unroll
        for (int p = 0; p < 4; p++) {
#pragma unroll
            for (int i = 0; i < 2; i++) {
                int row = crow + i * 64;
                int grow = (p < 2) ? (bm + row) : (bn + row);
                const __half* src = srcs[p] + (size_t)grow * D_MODEL + k0 + cch;
                uint32_t dst = sbase + (((stage * 4 + p) * PLANE) + row * PSTR + cch) * 2;
                cp_async16(dst, src);
            }
        }
        CP_COMMIT();
    };

    float acc[2][8][4];
#pragma unroll
    for (int mi = 0; mi < 2; mi++)
#pragma unroll
        for (int ni = 0; ni < 8; ni++)
#pragma unroll
            for (int q = 0; q < 4; q++) acc[mi][ni][q] = 0.f;

    issue(0, 0);
    issue(1, 32);

    for (int it = 0; it < NITER; it++) {
        const int s = it & 1;
        CP_WAIT1();
        __syncthreads();

        const __half* Ahs = psm + (s * 4 + 0) * PLANE;
        const __half* Als = psm + (s * 4 + 1) * PLANE;
        const __half* Bhs = psm + (s * 4 + 2) * PLANE;
        const __half* Bls = psm + (s * 4 + 3) * PLANE;

#pragma unroll
        for (int ck = 0; ck < 2; ck++) {
            const int kk = ck * 16 + lcol * 2;
            uint32_t ah[2][4], al_[2][4];
#pragma unroll
            for (int mi = 0; mi < 2; mi++) {
                const int r0 = wm + mi * 16 + lrow;
                ah[mi][0]  = *(const uint32_t*)&Ahs[r0 * PSTR + kk];
                ah[mi][1]  = *(const uint32_t*)&Ahs[(r0 + 8) * PSTR + kk];
                ah[mi][2]  = *(const uint32_t*)&Ahs[r0 * PSTR + kk + 8];
                ah[mi][3]  = *(const uint32_t*)&Ahs[(r0 + 8) * PSTR + kk + 8];
                al_[mi][0] = *(const uint32_t*)&Als[r0 * PSTR + kk];
                al_[mi][1] = *(const uint32_t*)&Als[(r0 + 8) * PSTR + kk];
                al_[mi][2] = *(const uint32_t*)&Als[r0 * PSTR + kk + 8];
                al_[mi][3] = *(const uint32_t*)&Als[(r0 + 8) * PSTR + kk + 8];
            }
            uint32_t bh[8][2], bl_[8][2];
#pragma unroll
            for (int ni = 0; ni < 8; ni++) {
                const int rb = wn + ni * 8 + lrow;
                bh[ni][0]  = *(const uint32_t*)&Bhs[rb * PSTR + kk];
                bh[ni][1]  = *(const uint32_t*)&Bhs[rb * PSTR + kk + 8];
                bl_[ni][0] = *(const uint32_t*)&Bls[rb * PSTR + kk];
                bl_[ni][1] = *(const uint32_t*)&Bls[rb * PSTR + kk + 8];
            }
#pragma unroll
            for (int ni = 0; ni < 8; ni++)
#pragma unroll
                for (int mi = 0; mi < 2; mi++)
                    mma_f16(acc[mi][ni], ah[mi], bh[ni]);
#pragma unroll
            for (int ni = 0; ni < 8; ni++)
#pragma unroll
                for (int mi = 0; mi < 2; mi++)
                    mma_f16(acc[mi][ni], ah[mi], bl_[ni]);
#pragma unroll
            for (int ni = 0; ni < 8; ni++)
#pragma unroll
                for (int mi = 0; mi < 2; mi++)
                    mma_f16(acc[mi][ni], al_[mi], bh[ni]);
        }
        __syncthreads();   // done reading stage s before reissuing into it

        if (it + 2 < NITER) issue(s, (it + 2) * 32);
        else CP_COMMIT();  // empty group keeps wait_group accounting aligned
    }

    // epilogue
    const long oh = (z == 0) ? KPH_ : QPH_;
    const long ol = (z == 0) ? KPL_ : QPL_;
#pragma unroll
    for (int mi = 0; mi < 2; mi++) {
        const int row = bm + wm + mi * 16 + lrow;
#pragma unroll
        for (int ni = 0; ni < 8; ni++) {
            const int col = bn + wn + ni * 8 + lcol * 2;
            const float b0 = bias[col], b1 = bias[col + 1];
            float v0 = acc[mi][ni][0] + b0, v1 = acc[mi][ni][1] + b1;
            float v2 = acc[mi][ni][2] + b0, v3 = acc[mi][ni][3] + b1;
            if (z == 0) {
                v0 = tanhf(v0); v1 = tanhf(v1);
                v2 = tanhf(v2); v3 = tanhf(v3);
            }
            if (z <= 1) {
                if (row < M) {
                    __half h0, l0, h1, l1;
                    split2h(v0, h0, l0); split2h(v1, h1, l1);
                    *(__half2*)&poolw[oh + (size_t)row * D_MODEL + col] = __halves2half2(h0, h1);
                    *(__half2*)&poolw[ol + (size_t)row * D_MODEL + col] = __halves2half2(l0, l1);
                }
                if (row + 8 < M) {
                    __half h2, l2, h3, l3;
                    split2h(v2, h2, l2); split2h(v3, h3, l3);
                    *(__half2*)&poolw[oh + (size_t)(row + 8) * D_MODEL + col] = __halves2half2(h2, h3);
                    *(__half2*)&poolw[ol + (size_t)(row + 8) * D_MODEL + col] = __halves2half2(l2, l3);
                }
            } else {
                if (row < M)
                    *(float2*)&wqlout[(size_t)row * D_MODEL + col] = make_float2(v0, v1);
                if (row + 8 < M)
                    *(float2*)&wqlout[(size_t)(row + 8) * D_MODEL + col] = make_float2(v2, v3);
            }
        }
    }
}

// ============================================================
// Scores GEMM (fp16x3): per bz: C[m,t] = qproj . kproj over 64-k slice
// Block 64x128, K=64 single pass, 8 warps (2x4), warp tile 32x32.
// ============================================================
#define SSTRH 72
#define SC_SMEM_B ((64 * SSTRH * 2 + 128 * SSTRH * 2) * 2)   // 55296

__global__ void __launch_bounds__(256) scores_f16_kernel(
    const __half* __restrict__ pool, float* __restrict__ scores)
{
    extern __shared__ __align__(16) __half ssm[];
    __half* Ahs = ssm;
    __half* Als = Ahs + 64 * SSTRH;
    __half* Bhs = Als + 64 * SSTRH;
    __half* Bls = Bhs + 128 * SSTRH;

    const int bz = blockIdx.z, b = bz / NH, zz = bz % NH;
    const __half* Aph = pool + QPH_ + zz * HDIM;
    const __half* Apl = pool + QPL_ + zz * HDIM;
    const __half* Bph = pool + KPH_ + (size_t)b * T_LEN * D_MODEL + zz * HDIM;
    const __half* Bpl = pool + KPL_ + (size_t)b * T_LEN * D_MODEL + zz * HDIM;
    float* Cb = scores + (size_t)bz * R_ROWS * T_LEN;

    const int tid = threadIdx.x;
    const int warp = tid >> 5, lane = tid & 31;
    const int wm = (warp >> 2) * 32, wn = (warp & 3) * 32;
    const int mbase = blockIdx.y * 64, nbase = blockIdx.x * 128;
    const int lrow = lane >> 2, lcol = lane & 3;
    const uint4 z4 = make_uint4(0u, 0u, 0u, 0u);

#pragma unroll
    for (int i = 0; i < 2; i++) {
        int fl = tid + 256 * i, row = fl >> 3, ch = fl & 7;
        bool ok = (mbase + row) < R_ROWS;
        size_t ga = (size_t)(mbase + row) * D_MODEL + ch * 8;
        *(uint4*)&Ahs[row * SSTRH + ch * 8] = ok ? *(const uint4*)&Aph[ga] : z4;
        *(uint4*)&Als[row * SSTRH + ch * 8] = ok ? *(const uint4*)&Apl[ga] : z4;
    }
#pragma unroll
    for (int i = 0; i < 4; i++) {
        int fl = tid + 256 * i, row = fl >> 3, ch = fl & 7;
        size_t gb = (size_t)(nbase + row) * D_MODEL + ch * 8;
        *(uint4*)&Bhs[row * SSTRH + ch * 8] = *(const uint4*)&Bph[gb];
        *(uint4*)&Bls[row * SSTRH + ch * 8] = *(const uint4*)&Bpl[gb];
    }
    __syncthreads();

    float acc[2][4][4];
#pragma unroll
    for (int mi = 0; mi < 2; mi++)
#pragma unroll
        for (int ni = 0; ni < 4; ni++)
#pragma unroll
            for (int q = 0; q < 4; q++) acc[mi][ni][q] = 0.f;

#pragma unroll
    for (int ck = 0; ck < 4; ck++) {
        const int kk = ck * 16 + lcol * 2;
        uint32_t ah[2][4], al_[2][4];
#pragma unroll
        for (int mi = 0; mi < 2; mi++) {
            const int r0 = wm + mi * 16 + lrow;
            ah[mi][0]  = *(const uint32_t*)&Ahs[r0 * SSTRH + kk];
            ah[mi][1]  = *(const uint32_t*)&Ahs[(r0 + 8) * SSTRH + kk];
            ah[mi][2]  = *(const uint32_t*)&Ahs[r0 * SSTRH + kk + 8];
            ah[mi][3]  = *(const uint32_t*)&Ahs[(r0 + 8) * SSTRH + kk + 8];
            al_[mi][0] = *(const uint32_t*)&Als[r0 * SSTRH + kk];
            al_[mi][1] = *(const uint32_t*)&Als[(r0 + 8) * SSTRH + kk];
            al_[mi][2] = *(const uint32_t*)&Als[r0 * SSTRH + kk + 8];
            al_[mi][3] = *(const uint32_t*)&Als[(r0 + 8) * SSTRH + kk + 8];
        }
        uint32_t bh[4][2], bl_[4][2];
#pragma unroll
        for (int ni = 0; ni < 4; ni++) {
            const int rb = wn + ni * 8 + lrow;
            bh[ni][0]  = *(const uint32_t*)&Bhs[rb * SSTRH + kk];
            bh[ni][1]  = *(const uint32_t*)&Bhs[rb * SSTRH + kk + 8];
            bl_[ni][0] = *(const uint32_t*)&Bls[rb * SSTRH + kk];
            bl_[ni][1] = *(const uint32_t*)&Bls[rb * SSTRH + kk + 8];
        }
#pragma unroll
        for (int ni = 0; ni < 4; ni++)
#pragma unroll
            for (int mi = 0; mi < 2; mi++)
                mma_f16(acc[mi][ni], ah[mi], bh[ni]);
#pragma unroll
        for (int ni = 0; ni < 4; ni++)
#pragma unroll
            for (int mi = 0; mi < 2; mi++)
                mma_f16(acc[mi][ni], ah[mi], bl_[ni]);
#pragma unroll
        for (int ni = 0; ni < 4; ni++)
#pragma unroll
            for (int mi = 0; mi < 2; mi++)
                mma_f16(acc[mi][ni], al_[mi], bh[ni]);
    }

#pragma unroll
    for (int mi = 0; mi < 2; mi++) {
        const int row = mbase + wm + mi * 16 + lrow;
#pragma unroll
        for (int ni = 0; ni < 4; ni++) {
            const int col = nbase + wn + ni * 8 + lcol * 2;
            if (row < R_ROWS)
                *(float2*)&Cb[(size_t)row * T_LEN + col] =
                    make_float2(acc[mi][ni][0], acc[mi][ni][1]);
            if (row + 8 < R_ROWS)
                *(float2*)&Cb[(size_t)(row + 8) * T_LEN + col] =
                    make_float2(acc[mi][ni][2], acc[mi][ni][3]);
        }
    }
}

// ============================================================
// Softmax over t for 4 synonym rows -> combined mean weights
// ============================================================
__global__ void __launch_bounds__(128) softmax_combine_kernel(
    const float* __restrict__ scores, float* __restrict__ w)
{
    __shared__ float ex[4][1024];
    __shared__ float invl[4];
    const int blk = blockIdx.x;
    const int bz = blk / C_CLS, c = blk % C_CLS;
    const int warp = threadIdx.x >> 5, lane = threadIdx.x & 31;

    const float* row = scores + ((size_t)bz * R_ROWS + c * 4 + warp) * T_LEN;

    float m = -INFINITY;
    for (int t = lane; t < T_LEN; t += 32) m = fmaxf(m, row[t]);
#pragma unroll
    for (int o = 16; o > 0; o >>= 1) m = fmaxf(m, __shfl_xor_sync(0xffffffffu, m, o));

    float ssum = 0.f;
    for (int t = lane; t < T_LEN; t += 32) {
        float e = expf(row[t] - m);
        ex[warp][t] = e;
        ssum += e;
    }
#pragma unroll
    for (int o = 16; o > 0; o >>= 1) ssum += __shfl_xor_sync(0xffffffffu, ssum, o);
    if (lane == 0) invl[warp] = 0.25f / ssum;
    __syncthreads();

    float* wr = w + ((size_t)bz * C_CLS + c) * T_LEN;
    for (int t = threadIdx.x; t < T_LEN; t += 128)
        wr[t] = ex[0][t] * invl[0] + ex[1][t] * invl[1]
              + ex[2][t] * invl[2] + ex[3][t] * invl[3];
}

// ============================================================
// Fused m2 + final:  per bz, t-tile:
//   m2[t,c] = sum_h tanh(H[b,t,z*64+h]) * wql[c,z*64+h]
//   out[b,c] += sum_t w[bz,c,t] * m2[t,c]     (atomicAdd)
// smem padded to 68 (272B stride = 16B multiple; 65-pad traps)
// ============================================================
__global__ void __launch_bounds__(256) m2_fused_kernel(
    const float* __restrict__ H, const float* __restrict__ wql,
    const float* __restrict__ w, float* __restrict__ out)
{
    const int bz = blockIdx.z;
    const int b = bz / NH, z = bz % NH;
    const int tbase = blockIdx.y * 64;

    __shared__ float Qs[64][68];   // [h][t-local] = tanh(H)
    __shared__ float Ks[64][68];   // [h][c]       = wql

    const int tid = threadIdx.x;

#pragma unroll
    for (int i = 0; i < 4; i++) {
        int fl = tid + 256 * i;
        int row = fl >> 4;            // t-local 0..63
        int hc = (fl & 15) * 4;
        float4 v = *(const float4*)&H[(size_t)(b * T_LEN + tbase + row) * D_MODEL + z * HDIM + hc];
        Qs[hc + 0][row] = tanhf(v.x); Qs[hc + 1][row] = tanhf(v.y);
        Qs[hc + 2][row] = tanhf(v.z); Qs[hc + 3][row] = tanhf(v.w);
    }
#pragma unroll
    for (int i = 0; i < 4; i++) {
        int fl = tid + 256 * i;
        int row = fl >> 4;            // c 0..63
        int hc = (fl & 15) * 4;
        float4 v = make_float4(0.f, 0.f, 0.f, 0.f);
        if (row < C_CLS)
            v = *(const float4*)&wql[(size_t)row * D_MODEL + z * HDIM + hc];
        Ks[hc + 0][row] = v.x; Ks[hc + 1][row] = v.y;
        Ks[hc + 2][row] = v.z; Ks[hc + 3][row] = v.w;
    }
    __syncthreads();

    const int tx = tid & 15, ty = tid >> 4;
    float acc[4][4];
#pragma unroll
    for (int i = 0; i < 4; i++)
#pragma unroll
        for (int j = 0; j < 4; j++) acc[i][j] = 0.f;

#pragma unroll
    for (int h = 0; h < 64; h++) {
        float ar[4], br[4];
        *(float4*)&ar[0] = *(float4*)&Qs[h][ty * 4];
        *(float4*)&br[0] = *(float4*)&Ks[h][tx * 4];
#pragma unroll
        for (int i = 0; i < 4; i++)
#pragma unroll
            for (int j = 0; j < 4; j++)
                acc[i][j] = fmaf(ar[i], br[j], acc[i][j]);
    }
    __syncthreads();

    float* pm = &Qs[0][0];             // [16][64] partials
    float p[4];
#pragma unroll
    for (int j = 0; j < 4; j++) {
        const int c = tx * 4 + j;
        p[j] = 0.f;
        if (c < C_CLS) {
            float4 wv = *(const float4*)&w[((size_t)bz * C_CLS + c) * T_LEN + tbase + ty * 4];
            p[j] = acc[0][j] * wv.x + acc[1][j] * wv.y
                 + acc[2][j] * wv.z + acc[3][j] * wv.w;
        }
        pm[ty * 64 + tx * 4 + j] = p[j];
    }
    __syncthreads();

    if (tid < 64 && tid < C_CLS) {
        float s = 0.f;
#pragma unroll
        for (int r = 0; r < 16; r++) s += pm[r * 64 + tid];
        atomicAdd(&out[b * C_CLS + tid], s);
    }
}

// ============================================================
extern "C" void kernel_launch(void* const* d_in, const int* in_sizes, int n_in,
                              void* d_out, int out_size)
{
    const float* Q   = (const float*)d_in[0];
    const float* H   = (const float*)d_in[1];
    const float* ql  = (const float*)d_in[2];
    const float* WQw = (const float*)d_in[3];
    const float* WQb = (const float*)d_in[4];
    const float* WKw = (const float*)d_in[5];
    const float* WKb = (const float*)d_in[6];
    const float* WVw = (const float*)d_in[7];
    const float* WVb = (const float*)d_in[8];
    float* out = (float*)d_out;

    __half* pool;
    float *wql, *scores, *w;
    cudaGetSymbolAddress((void**)&pool,   g_hf);
    cudaGetSymbolAddress((void**)&wql,    g_wql);
    cudaGetSymbolAddress((void**)&scores, g_scores);
    cudaGetSymbolAddress((void**)&w,      g_w);

    cudaFuncSetAttribute(proj_f16_kernel,
                         cudaFuncAttributeMaxDynamicSharedMemorySize, PROJ_SMEM);
    cudaFuncSetAttribute(scores_f16_kernel,
                         cudaFuncAttributeMaxDynamicSharedMemorySize, SC_SMEM_B);

    zero_out_kernel<<<1, 256>>>(out);

    // pre-split fp32 -> fp16 hi/lo (one launch for H, Q, ql)
    split_all_kernel<<<(N_H + N_Q + N_QL + 255) / 256, 256>>>(H, Q, ql, pool);
    split_transpose_kernel<<<dim3(24, 24, 3), 256>>>(WKw, WQw, WVw, pool);

    // fused projections (cp.async double-buffered, 2 blocks/SM)
    proj_f16_kernel<<<dim3(6, 32, 3), 256, PROJ_SMEM>>>(pool, pool, WKb, WQb, WVb, wql);

    // scores per (b,z) on fp16x3 mma
    scores_f16_kernel<<<dim3(8, 4, BZ), 256, SC_SMEM_B>>>(pool, scores);

    // softmax + synonym-mean combine
    softmax_combine_kernel<<<BZ * C_CLS, 128>>>(scores, w);

    // fused m2 + weighted reduce into out
    m2_fused_kernel<<<dim3(1, 16, BZ), 256>>>(H, wql, w, out);
}

// round 12
// speedup vs baseline: 2.6648x; 1.0297x over previous
#include <cuda_runtime.h>
#include <cuda_fp16.h>
#include <math.h>
#include <stdint.h>

// Problem dims (fixed)
#define D_MODEL 768
#define NH      12
#define HDIM    64
#define C_CLS   50
#define B_BATCH 4
#define T_LEN   1024
#define R_ROWS  200
#define BZ      48

// -------- fp32 scratch (explicitly aligned for vector access) --------
__device__ __align__(256) float g_wql[C_CLS * D_MODEL];
__device__ __align__(256) float g_scores[BZ * R_ROWS * T_LEN];
__device__ __align__(256) float g_w[BZ * C_CLS * T_LEN];

// -------- fp16 hi/lo split pool (offsets in halves; all 16B-multiples) --------
#define AH_H   0L
#define AH_L   3145728L
#define WKT_H  6291456L
#define WQT_H  7471104L
#define WVT_H  8650752L
#define W_PL   589824L
#define QH_    9830400L
#define QL_    9984000L
#define QLH_   10137600L
#define QLL_   10176000L
#define KPH_   10214400L
#define KPL_   13360128L
#define QPH_   16505856L
#define QPL_   16659456L
#define POOL_SZ 16813056L
__device__ __align__(256) __half g_hf[POOL_SZ];

// ============================================================
// helpers
// ============================================================
__device__ __forceinline__ void split2h(float v, __half& h, __half& l) {
    h = __float2half_rn(v);
    l = __float2half_rn(v - __half2float(h));
}

__device__ __forceinline__ void mma_f16(float* c, const uint32_t* a, const uint32_t* b) {
    asm volatile(
        "mma.sync.aligned.m16n8k16.row.col.f32.f16.f16.f32 "
        "{%0,%1,%2,%3}, {%4,%5,%6,%7}, {%8,%9}, {%0,%1,%2,%3};"
        : "+f"(c[0]), "+f"(c[1]), "+f"(c[2]), "+f"(c[3])
        : "r"(a[0]), "r"(a[1]), "r"(a[2]), "r"(a[3]), "r"(b[0]), "r"(b[1]));
}

__device__ __forceinline__ void ldsm_x4(uint32_t* r, uint32_t addr) {
    asm volatile(
        "ldmatrix.sync.aligned.m8n8.x4.shared.b16 {%0,%1,%2,%3}, [%4];"
        : "=r"(r[0]), "=r"(r[1]), "=r"(r[2]), "=r"(r[3]) : "r"(addr));
}

__device__ __forceinline__ uint32_t smem_u32(const void* p) {
    uint32_t a;
    asm("{ .reg .u64 t; cvta.to.shared.u64 t, %1; cvt.u32.u64 %0, t; }"
        : "=r"(a) : "l"(p));
    return a;
}
__device__ __forceinline__ void cp_async16(uint32_t dst, const void* src) {
    asm volatile("cp.async.cg.shared.global [%0], [%1], 16;" :: "r"(dst), "l"(src));
}
#define CP_COMMIT() asm volatile("cp.async.commit_group;")
#define CP_WAIT1()  asm volatile("cp.async.wait_group 1;")

// ============================================================
// zero output (out is poisoned; we accumulate with atomics)
// ============================================================
__global__ void zero_out_kernel(float* out) {
    if (threadIdx.x < B_BATCH * C_CLS) out[threadIdx.x] = 0.f;
}

// ============================================================
// fp32 -> (hi, lo) fp16 planes, all three inputs in one launch
// ============================================================
#define N_H  (B_BATCH * T_LEN * D_MODEL)   // 3145728
#define N_Q  (R_ROWS * D_MODEL)            // 153600
#define N_QL (C_CLS * D_MODEL)             // 38400

__global__ void __launch_bounds__(256) split_all_kernel(
    const float* __restrict__ H, const float* __restrict__ Q,
    const float* __restrict__ ql, __half* __restrict__ pool)
{
    int i = blockIdx.x * blockDim.x + threadIdx.x;
    float v; long oh, ol; int idx;
    if (i < N_H) {
        v = H[i]; oh = AH_H; ol = AH_L; idx = i;
    } else if (i < N_H + N_Q) {
        idx = i - N_H; v = Q[idx]; oh = QH_; ol = QL_;
    } else if (i < N_H + N_Q + N_QL) {
        idx = i - N_H - N_Q; v = ql[idx]; oh = QLH_; ol = QLL_;
    } else return;
    __half h, l;
    split2h(v, h, l);
    pool[oh + idx] = h; pool[ol + idx] = l;
}

// W[k][n] fp32 -> Wt hi/lo [n][k] fp16 (z selects WK/WQ/WV)
__global__ void __launch_bounds__(256) split_transpose_kernel(
    const float* __restrict__ W0, const float* __restrict__ W1,
    const float* __restrict__ W2, __half* __restrict__ pool)
{
    __shared__ float t[32][33];
    const float* W = (blockIdx.z == 0) ? W0 : (blockIdx.z == 1) ? W1 : W2;
    const long oh = (blockIdx.z == 0) ? WKT_H : (blockIdx.z == 1) ? WQT_H : WVT_H;
    const long ol = oh + W_PL;
    const int k0 = blockIdx.y * 32, n0 = blockIdx.x * 32;
    const int tx = threadIdx.x & 31, ty = threadIdx.x >> 5;
#pragma unroll
    for (int j = 0; j < 32; j += 8)
        t[ty + j][tx] = W[(size_t)(k0 + ty + j) * D_MODEL + n0 + tx];
    __syncthreads();
#pragma unroll
    for (int j = 0; j < 32; j += 8) {
        float v = t[tx][ty + j];
        __half h, l;
        split2h(v, h, l);
        size_t idx = (size_t)(n0 + ty + j) * D_MODEL + k0 + tx;
        pool[oh + idx] = h; pool[ol + idx] = l;
    }
}

// ============================================================
// Fused projection GEMM (fp16x3, cp.async + ldmatrix):
//  z=0: kproj = tanh(H@WK+b)  -> fp16 hi/lo planes   (M=4096)
//  z=1: qproj = Q@WQ+b        -> fp16 hi/lo planes   (M=200)
//  z=2: wql   = ql@WV+b       -> fp32                (M=50)
// Block 128x128, BK=32, 256 thr = 8 warps (4x2), warp tile 32x64.
// ============================================================
#define PSTR 40                  // halves per smem row (80B = 16B multiple)
#define PLANE (128 * PSTR)       // halves per plane
#define PROJ_SMEM (2 * 4 * PLANE * 2)   // 81920 bytes
#define NITER 24                 // 768 / 32

__global__ void __launch_bounds__(256, 2) proj_f16_kernel(
    const __half* __restrict__ pool, __half* __restrict__ poolw,
    const float* __restrict__ WKb, const float* __restrict__ WQb,
    const float* __restrict__ WVb, float* __restrict__ wqlout)
{
    const int z = blockIdx.z;
    int M; const __half *Ah, *Al, *Bh, *Bl; const float* bias;
    if (z == 0) {
        M = 4096; Ah = pool + AH_H; Al = pool + AH_L;
        Bh = pool + WKT_H; Bl = pool + WKT_H + W_PL; bias = WKb;
    } else if (z == 1) {
        if (blockIdx.y >= 2) return;
        M = R_ROWS; Ah = pool + QH_; Al = pool + QL_;
        Bh = pool + WQT_H; Bl = pool + WQT_H + W_PL; bias = WQb;
    } else {
        if (blockIdx.y >= 1) return;
        M = C_CLS; Ah = pool + QLH_; Al = pool + QLL_;
        Bh = pool + WVT_H; Bl = pool + WVT_H + W_PL; bias = WVb;
    }

    extern __shared__ __align__(16) __half psm[];
    const uint32_t sbase = smem_u32(psm);

    const int tid = threadIdx.x;
    const int warp = tid >> 5, lane = tid & 31;
    const int wm = (warp >> 1) * 32, wn = (warp & 1) * 64;
    const int bm = blockIdx.y * 128, bn = blockIdx.x * 128;
    const int lrow = lane >> 2, lcol = lane & 3;

    // ldmatrix lane-address components
    const int a_r = lane & 15, a_c = (lane >> 4) << 3;                 // A x4
    const int b_r = ((lane >> 4) << 3) + (lane & 7);                   // B x4 row
    const int b_c = ((lane >> 3) & 1) << 3;                            // B x4 col

    const int crow = tid >> 2, cch = (tid & 3) * 8;  // cp.async copy indices

    const __half* srcs[4] = { Ah, Al, Bh, Bl };
    auto issue = [&](int stage, int k0) {
#pragma unroll
        for (int p = 0; p < 4; p++) {
#pragma unroll
            for (int i = 0; i < 2; i++) {
                int row = crow + i * 64;
                int grow = (p < 2) ? (bm + row) : (bn + row);
                const __half* src = srcs[p] + (size_t)grow * D_MODEL + k0 + cch;
                uint32_t dst = sbase + (((stage * 4 + p) * PLANE) + row * PSTR + cch) * 2;
                cp_async16(dst, src);
            }
        }
        CP_COMMIT();
    };

    float acc[2][8][4];
#pragma unroll
    for (int mi = 0; mi < 2; mi++)
#pragma unroll
        for (int ni = 0; ni < 8; ni++)
#pragma unroll
            for (int q = 0; q < 4; q++) acc[mi][ni][q] = 0.f;

    issue(0, 0);
    issue(1, 32);

    for (int it = 0; it < NITER; it++) {
        const int s = it & 1;
        CP_WAIT1();
        __syncthreads();

        const uint32_t ahs_u = sbase + ((s * 4 + 0) * PLANE) * 2;
        const uint32_t als_u = sbase + ((s * 4 + 1) * PLANE) * 2;
        const uint32_t bhs_u = sbase + ((s * 4 + 2) * PLANE) * 2;
        const uint32_t bls_u = sbase + ((s * 4 + 3) * PLANE) * 2;

#pragma unroll
        for (int ck = 0; ck < 2; ck++) {
            const int kk = ck * 16;
            uint32_t ah[2][4], al_[2][4];
#pragma unroll
            for (int mi = 0; mi < 2; mi++) {
                const uint32_t aoff = ((wm + mi * 16 + a_r) * PSTR + kk + a_c) * 2;
                ldsm_x4(ah[mi],  ahs_u + aoff);
                ldsm_x4(al_[mi], als_u + aoff);
            }
            uint32_t bh[8][2], bl_[8][2];
#pragma unroll
            for (int nj = 0; nj < 4; nj++) {
                const uint32_t boff = ((wn + nj * 16 + b_r) * PSTR + kk + b_c) * 2;
                uint32_t q[4];
                ldsm_x4(q, bhs_u + boff);
                bh[nj * 2][0] = q[0]; bh[nj * 2][1] = q[1];
                bh[nj * 2 + 1][0] = q[2]; bh[nj * 2 + 1][1] = q[3];
                ldsm_x4(q, bls_u + boff);
                bl_[nj * 2][0] = q[0]; bl_[nj * 2][1] = q[1];
                bl_[nj * 2 + 1][0] = q[2]; bl_[nj * 2 + 1][1] = q[3];
            }
#pragma unroll
            for (int ni = 0; ni < 8; ni++)
#pragma unroll
                for (int mi = 0; mi < 2; mi++)
                    mma_f16(acc[mi][ni], ah[mi], bh[ni]);
#pragma unroll
            for (int ni = 0; ni < 8; ni++)
#pragma unroll
                for (int mi = 0; mi < 2; mi++)
                    mma_f16(acc[mi][ni], ah[mi], bl_[ni]);
#pragma unroll
            for (int ni = 0; ni < 8; ni++)
#pragma unroll
                for (int mi = 0; mi < 2; mi++)
                    mma_f16(acc[mi][ni], al_[mi], bh[ni]);
        }
        __syncthreads();

        if (it + 2 < NITER) issue(s, (it + 2) * 32);
        else CP_COMMIT();
    }

    // epilogue
    const long oh = (z == 0) ? KPH_ : QPH_;
    const long ol = (z == 0) ? KPL_ : QPL_;
#pragma unroll
    for (int mi = 0; mi < 2; mi++) {
        const int row = bm + wm + mi * 16 + lrow;
#pragma unroll
        for (int ni = 0; ni < 8; ni++) {
            const int col = bn + wn + ni * 8 + lcol * 2;
            const float b0 = bias[col], b1 = bias[col + 1];
            float v0 = acc[mi][ni][0] + b0, v1 = acc[mi][ni][1] + b1;
            float v2 = acc[mi][ni][2] + b0, v3 = acc[mi][ni][3] + b1;
            if (z == 0) {
                v0 = tanhf(v0); v1 = tanhf(v1);
                v2 = tanhf(v2); v3 = tanhf(v3);
            }
            if (z <= 1) {
                if (row < M) {
                    __half h0, l0, h1, l1;
                    split2h(v0, h0, l0); split2h(v1, h1, l1);
                    *(__half2*)&poolw[oh + (size_t)row * D_MODEL + col] = __halves2half2(h0, h1);
                    *(__half2*)&poolw[ol + (size_t)row * D_MODEL + col] = __halves2half2(l0, l1);
                }
                if (row + 8 < M) {
                    __half h2, l2, h3, l3;
                    split2h(v2, h2, l2); split2h(v3, h3, l3);
                    *(__half2*)&poolw[oh + (size_t)(row + 8) * D_MODEL + col] = __halves2half2(h2, h3);
                    *(__half2*)&poolw[ol + (size_t)(row + 8) * D_MODEL + col] = __halves2half2(l2, l3);
                }
            } else {
                if (row < M)
                    *(float2*)&wqlout[(size_t)row * D_MODEL + col] = make_float2(v0, v1);
                if (row + 8 < M)
                    *(float2*)&wqlout[(size_t)(row + 8) * D_MODEL + col] = make_float2(v2, v3);
            }
        }
    }
}

// ============================================================
// Scores GEMM (fp16x3, ldmatrix): per bz over 64-k slice
// Block 64x128, K=64 single pass, 8 warps (2x4), warp tile 32x32.
// ============================================================
#define SSTRH 72
#define SC_SMEM_B ((64 * SSTRH * 2 + 128 * SSTRH * 2) * 2)   // 55296

__global__ void __launch_bounds__(256) scores_f16_kernel(
    const __half* __restrict__ pool, float* __restrict__ scores)
{
    extern __shared__ __align__(16) __half ssm[];
    __half* Ahs = ssm;
    __half* Als = Ahs + 64 * SSTRH;
    __half* Bhs = Als + 64 * SSTRH;
    __half* Bls = Bhs + 128 * SSTRH;

    const int bz = blockIdx.z, b = bz / NH, zz = bz % NH;
    const __half* Aph = pool + QPH_ + zz * HDIM;
    const __half* Apl = pool + QPL_ + zz * HDIM;
    const __half* Bph = pool + KPH_ + (size_t)b * T_LEN * D_MODEL + zz * HDIM;
    const __half* Bpl = pool + KPL_ + (size_t)b * T_LEN * D_MODEL + zz * HDIM;
    float* Cb = scores + (size_t)bz * R_ROWS * T_LEN;

    const int tid = threadIdx.x;
    const int warp = tid >> 5, lane = tid & 31;
    const int wm = (warp >> 2) * 32, wn = (warp & 3) * 32;
    const int mbase = blockIdx.y * 64, nbase = blockIdx.x * 128;
    const int lrow = lane >> 2, lcol = lane & 3;
    const uint4 z4 = make_uint4(0u, 0u, 0u, 0u);

    const int a_r = lane & 15, a_c = (lane >> 4) << 3;
    const int b_r = ((lane >> 4) << 3) + (lane & 7);
    const int b_c = ((lane >> 3) & 1) << 3;

#pragma unroll
    for (int i = 0; i < 2; i++) {
        int fl = tid + 256 * i, row = fl >> 3, ch = fl & 7;
        bool ok = (mbase + row) < R_ROWS;
        size_t ga = (size_t)(mbase + row) * D_MODEL + ch * 8;
        *(uint4*)&Ahs[row * SSTRH + ch * 8] = ok ? *(const uint4*)&Aph[ga] : z4;
        *(uint4*)&Als[row * SSTRH + ch * 8] = ok ? *(const uint4*)&Apl[ga] : z4;
    }
#pragma unroll
    for (int i = 0; i < 4; i++) {
        int fl = tid + 256 * i, row = fl >> 3, ch = fl & 7;
        size_t gb = (size_t)(nbase + row) * D_MODEL + ch * 8;
        *(uint4*)&Bhs[row * SSTRH + ch * 8] = *(const uint4*)&Bph[gb];
        *(uint4*)&Bls[row * SSTRH + ch * 8] = *(const uint4*)&Bpl[gb];
    }
    __syncthreads();

    const uint32_t ahs_u = smem_u32(Ahs), als_u = smem_u32(Als);
    const uint32_t bhs_u = smem_u32(Bhs), bls_u = smem_u32(Bls);

    float acc[2][4][4];
#pragma unroll
    for (int mi = 0; mi < 2; mi++)
#pragma unroll
        for (int ni = 0; ni < 4; ni++)
#pragma unroll
            for (int q = 0; q < 4; q++) acc[mi][ni][q] = 0.f;

#pragma unroll
    for (int ck = 0; ck < 4; ck++) {
        const int kk = ck * 16;
        uint32_t ah[2][4], al_[2][4];
#pragma unroll
        for (int mi = 0; mi < 2; mi++) {
            const uint32_t aoff = ((wm + mi * 16 + a_r) * SSTRH + kk + a_c) * 2;
            ldsm_x4(ah[mi],  ahs_u + aoff);
            ldsm_x4(al_[mi], als_u + aoff);
        }
        uint32_t bh[4][2], bl_[4][2];
#pragma unroll
        for (int nj = 0; nj < 2; nj++) {
            const uint32_t boff = ((wn + nj * 16 + b_r) * SSTRH + kk + b_c) * 2;
            uint32_t q[4];
            ldsm_x4(q, bhs_u + boff);
            bh[nj * 2][0] = q[0]; bh[nj * 2][1] = q[1];
            bh[nj * 2 + 1][0] = q[2]; bh[nj * 2 + 1][1] = q[3];
            ldsm_x4(q, bls_u + boff);
            bl_[nj * 2][0] = q[0]; bl_[nj * 2][1] = q[1];
            bl_[nj * 2 + 1][0] = q[2]; bl_[nj * 2 + 1][1] = q[3];
        }
#pragma unroll
        for (int ni = 0; ni < 4; ni++)
#pragma unroll
            for (int mi = 0; mi < 2; mi++)
                mma_f16(acc[mi][ni], ah[mi], bh[ni]);
#pragma unroll
        for (int ni = 0; ni < 4; ni++)
#pragma unroll
            for (int mi = 0; mi < 2; mi++)
                mma_f16(acc[mi][ni], ah[mi], bl_[ni]);
#pragma unroll
        for (int ni = 0; ni < 4; ni++)
#pragma unroll
            for (int mi = 0; mi < 2; mi++)
                mma_f16(acc[mi][ni], al_[mi], bh[ni]);
    }

#pragma unroll
    for (int mi = 0; mi < 2; mi++) {
        const int row = mbase + wm + mi * 16 + lrow;
#pragma unroll
        for (int ni = 0; ni < 4; ni++) {
            const int col = nbase + wn + ni * 8 + lcol * 2;
            if (row < R_ROWS)
                *(float2*)&Cb[(size_t)row * T_LEN + col] =
                    make_float2(acc[mi][ni][0], acc[mi][ni][1]);
            if (row + 8 < R_ROWS)
                *(float2*)&Cb[(size_t)(row + 8) * T_LEN + col] =
                    make_float2(acc[mi][ni][2], acc[mi][ni][3]);
        }
    }
}

// ============================================================
// Softmax over t for 4 synonym rows -> combined mean weights
// ============================================================
__global__ void __launch_bounds__(128) softmax_combine_kernel(
    const float* __restrict__ scores, float* __restrict__ w)
{
    __shared__ float ex[4][1024];
    __shared__ float invl[4];
    const int blk = blockIdx.x;
    const int bz = blk / C_CLS, c = blk % C_CLS;
    const int warp = threadIdx.x >> 5, lane = threadIdx.x & 31;

    const float* row = scores + ((size_t)bz * R_ROWS + c * 4 + warp) * T_LEN;

    float m = -INFINITY;
    for (int t = lane; t < T_LEN; t += 32) m = fmaxf(m, row[t]);
#pragma unroll
    for (int o = 16; o > 0; o >>= 1) m = fmaxf(m, __shfl_xor_sync(0xffffffffu, m, o));

    float ssum = 0.f;
    for (int t = lane; t < T_LEN; t += 32) {
        float e = expf(row[t] - m);
        ex[warp][t] = e;
        ssum += e;
    }
#pragma unroll
    for (int o = 16; o > 0; o >>= 1) ssum += __shfl_xor_sync(0xffffffffu, ssum, o);
    if (lane == 0) invl[warp] = 0.25f / ssum;
    __syncthreads();

    float* wr = w + ((size_t)bz * C_CLS + c) * T_LEN;
    for (int t = threadIdx.x; t < T_LEN; t += 128)
        wr[t] = ex[0][t] * invl[0] + ex[1][t] * invl[1]
              + ex[2][t] * invl[2] + ex[3][t] * invl[3];
}

// ============================================================
// Fused m2 + final (smem pad 68 = 272B stride, 16B multiple)
// ============================================================
__global__ void __launch_bounds__(256) m2_fused_kernel(
    const float* __restrict__ H, const float* __restrict__ wql,
    const float* __restrict__ w, float* __restrict__ out)
{
    const int bz = blockIdx.z;
    const int b = bz / NH, z = bz % NH;
    const int tbase = blockIdx.y * 64;

    __shared__ float Qs[64][68];
    __shared__ float Ks[64][68];

    const int tid = threadIdx.x;

#pragma unroll
    for (int i = 0; i < 4; i++) {
        int fl = tid + 256 * i;
        int row = fl >> 4;
        int hc = (fl & 15) * 4;
        float4 v = *(const float4*)&H[(size_t)(b * T_LEN + tbase + row) * D_MODEL + z * HDIM + hc];
        Qs[hc + 0][row] = tanhf(v.x); Qs[hc + 1][row] = tanhf(v.y);
        Qs[hc + 2][row] = tanhf(v.z); Qs[hc + 3][row] = tanhf(v.w);
    }
#pragma unroll
    for (int i = 0; i < 4; i++) {
        int fl = tid + 256 * i;
        int row = fl >> 4;
        int hc = (fl & 15) * 4;
        float4 v = make_float4(0.f, 0.f, 0.f, 0.f);
        if (row < C_CLS)
            v = *(const float4*)&wql[(size_t)row * D_MODEL + z * HDIM + hc];
        Ks[hc + 0][row] = v.x; Ks[hc + 1][row] = v.y;
        Ks[hc + 2][row] = v.z; Ks[hc + 3][row] = v.w;
    }
    __syncthreads();

    const int tx = tid & 15, ty = tid >> 4;
    float acc[4][4];
#pragma unroll
    for (int i = 0; i < 4; i++)
#pragma unroll
        for (int j = 0; j < 4; j++) acc[i][j] = 0.f;

#pragma unroll
    for (int h = 0; h < 64; h++) {
        float ar[4], br[4];
        *(float4*)&ar[0] = *(float4*)&Qs[h][ty * 4];
        *(float4*)&br[0] = *(float4*)&Ks[h][tx * 4];
#pragma unroll
        for (int i = 0; i < 4; i++)
#pragma unroll
            for (int j = 0; j < 4; j++)
                acc[i][j] = fmaf(ar[i], br[j], acc[i][j]);
    }
    __syncthreads();

    float* pm = &Qs[0][0];
    float p[4];
#pragma unroll
    for (int j = 0; j < 4; j++) {
        const int c = tx * 4 + j;
        p[j] = 0.f;
        if (c < C_CLS) {
            float4 wv = *(const float4*)&w[((size_t)bz * C_CLS + c) * T_LEN + tbase + ty * 4];
            p[j] = acc[0][j] * wv.x + acc[1][j] * wv.y
                 + acc[2][j] * wv.z + acc[3][j] * wv.w;
        }
        pm[ty * 64 + tx * 4 + j] = p[j];
    }
    __syncthreads();

    if (tid < 64 && tid < C_CLS) {
        float s = 0.f;
#pragma unroll
        for (int r = 0; r < 16; r++) s += pm[r * 64 + tid];
        atomicAdd(&out[b * C_CLS + tid], s);
    }
}

// ============================================================
extern "C" void kernel_launch(void* const* d_in, const int* in_sizes, int n_in,
                              void* d_out, int out_size)
{
    const float* Q   = (const float*)d_in[0];
    const float* H   = (const float*)d_in[1];
    const float* ql  = (const float*)d_in[2];
    const float* WQw = (const float*)d_in[3];
    const float* WQb = (const float*)d_in[4];
    const float* WKw = (const float*)d_in[5];
    const float* WKb = (const float*)d_in[6];
    const float* WVw = (const float*)d_in[7];
    const float* WVb = (const float*)d_in[8];
    float* out = (float*)d_out;

    __half* pool;
    float *wql, *scores, *w;
    cudaGetSymbolAddress((void**)&pool,   g_hf);
    cudaGetSymbolAddress((void**)&wql,    g_wql);
    cudaGetSymbolAddress((void**)&scores, g_scores);
    cudaGetSymbolAddress((void**)&w,      g_w);

    cudaFuncSetAttribute(proj_f16_kernel,
                         cudaFuncAttributeMaxDynamicSharedMemorySize, PROJ_SMEM);
    cudaFuncSetAttribute(scores_f16_kernel,
                         cudaFuncAttributeMaxDynamicSharedMemorySize, SC_SMEM_B);

    zero_out_kernel<<<1, 256>>>(out);

    split_all_kernel<<<(N_H + N_Q + N_QL + 255) / 256, 256>>>(H, Q, ql, pool);
    split_transpose_kernel<<<dim3(24, 24, 3), 256>>>(WKw, WQw, WVw, pool);

    proj_f16_kernel<<<dim3(6, 32, 3), 256, PROJ_SMEM>>>(pool, pool, WKb, WQb, WVb, wql);

    scores_f16_kernel<<<dim3(8, 4, BZ), 256, SC_SMEM_B>>>(pool, scores);

    softmax_combine_kernel<<<BZ * C_CLS, 128>>>(scores, w);

    m2_fused_kernel<<<dim3(1, 16, BZ), 256>>>(H, wql, w, out);
}

// round 13
// speedup vs baseline: 2.8778x; 1.0799x over previous
#include <cuda_runtime.h>
#include <cuda_fp16.h>
#include <math.h>
#include <stdint.h>

// Problem dims (fixed)
#define D_MODEL 768
#define NH      12
#define HDIM    64
#define C_CLS   50
#define B_BATCH 4
#define T_LEN   1024
#define R_ROWS  200
#define BZ      48

// -------- fp32 scratch (explicitly aligned for vector access) --------
__device__ __align__(256) float g_wql[C_CLS * D_MODEL];
__device__ __align__(256) float g_scores[BZ * R_ROWS * T_LEN];
__device__ __align__(256) float g_w[BZ * C_CLS * T_LEN];

// -------- fp16 hi/lo split pool (offsets in halves; all 16B-multiples) --------
#define AH_H   0L
#define AH_L   3145728L
#define WKT_H  6291456L
#define WQT_H  7471104L
#define WVT_H  8650752L
#define W_PL   589824L
#define QH_    9830400L
#define QL_    9984000L
#define QLH_   10137600L
#define QLL_   10176000L
#define KPH_   10214400L
#define KPL_   13360128L
#define QPH_   16505856L
#define QPL_   16659456L
#define POOL_SZ 16813056L
__device__ __align__(256) __half g_hf[POOL_SZ];

// ============================================================
// helpers
// ============================================================
__device__ __forceinline__ void split2h(float v, __half& h, __half& l) {
    h = __float2half_rn(v);
    l = __float2half_rn(v - __half2float(h));
}

__device__ __forceinline__ void mma_f16(float* c, const uint32_t* a, const uint32_t* b) {
    asm volatile(
        "mma.sync.aligned.m16n8k16.row.col.f32.f16.f16.f32 "
        "{%0,%1,%2,%3}, {%4,%5,%6,%7}, {%8,%9}, {%0,%1,%2,%3};"
        : "+f"(c[0]), "+f"(c[1]), "+f"(c[2]), "+f"(c[3])
        : "r"(a[0]), "r"(a[1]), "r"(a[2]), "r"(a[3]), "r"(b[0]), "r"(b[1]));
}

__device__ __forceinline__ void ldsm_x4(uint32_t* r, uint32_t addr) {
    asm volatile(
        "ldmatrix.sync.aligned.m8n8.x4.shared.b16 {%0,%1,%2,%3}, [%4];"
        : "=r"(r[0]), "=r"(r[1]), "=r"(r[2]), "=r"(r[3]) : "r"(addr));
}

__device__ __forceinline__ uint32_t smem_u32(const void* p) {
    uint32_t a;
    asm("{ .reg .u64 t; cvta.to.shared.u64 t, %1; cvt.u32.u64 %0, t; }"
        : "=r"(a) : "l"(p));
    return a;
}
__device__ __forceinline__ void cp_async16(uint32_t dst, const void* src) {
    asm volatile("cp.async.cg.shared.global [%0], [%1], 16;" :: "r"(dst), "l"(src));
}
#define CP_COMMIT() asm volatile("cp.async.commit_group;")
#define CP_WAIT1()  asm volatile("cp.async.wait_group 1;")

// ============================================================
// zero output (out is poisoned; we accumulate with atomics)
// ============================================================
__global__ void zero_out_kernel(float* out) {
    if (threadIdx.x < B_BATCH * C_CLS) out[threadIdx.x] = 0.f;
}

// ============================================================
// fp32 -> (hi, lo) fp16 planes, all three inputs in one launch
// ============================================================
#define N_H  (B_BATCH * T_LEN * D_MODEL)   // 3145728
#define N_Q  (R_ROWS * D_MODEL)            // 153600
#define N_QL (C_CLS * D_MODEL)             // 38400

__global__ void __launch_bounds__(256) split_all_kernel(
    const float* __restrict__ H, const float* __restrict__ Q,
    const float* __restrict__ ql, __half* __restrict__ pool)
{
    int i = blockIdx.x * blockDim.x + threadIdx.x;
    float v; long oh, ol; int idx;
    if (i < N_H) {
        v = H[i]; oh = AH_H; ol = AH_L; idx = i;
    } else if (i < N_H + N_Q) {
        idx = i - N_H; v = Q[idx]; oh = QH_; ol = QL_;
    } else if (i < N_H + N_Q + N_QL) {
        idx = i - N_H - N_Q; v = ql[idx]; oh = QLH_; ol = QLL_;
    } else return;
    __half h, l;
    split2h(v, h, l);
    pool[oh + idx] = h; pool[ol + idx] = l;
}

// W[k][n] fp32 -> Wt hi/lo [n][k] fp16 (z selects WK/WQ/WV)
__global__ void __launch_bounds__(256) split_transpose_kernel(
    const float* __restrict__ W0, const float* __restrict__ W1,
    const float* __restrict__ W2, __half* __restrict__ pool)
{
    __shared__ float t[32][33];
    const float* W = (blockIdx.z == 0) ? W0 : (blockIdx.z == 1) ? W1 : W2;
    const long oh = (blockIdx.z == 0) ? WKT_H : (blockIdx.z == 1) ? WQT_H : WVT_H;
    const long ol = oh + W_PL;
    const int k0 = blockIdx.y * 32, n0 = blockIdx.x * 32;
    const int tx = threadIdx.x & 31, ty = threadIdx.x >> 5;
#pragma unroll
    for (int j = 0; j < 32; j += 8)
        t[ty + j][tx] = W[(size_t)(k0 + ty + j) * D_MODEL + n0 + tx];
    __syncthreads();
#pragma unroll
    for (int j = 0; j < 32; j += 8) {
        float v = t[tx][ty + j];
        __half h, l;
        split2h(v, h, l);
        size_t idx = (size_t)(n0 + ty + j) * D_MODEL + k0 + tx;
        pool[oh + idx] = h; pool[ol + idx] = l;
    }
}

// ============================================================
// Fused projection GEMM (fp16x3, cp.async + ldmatrix, high-occ):
//  z=0: kproj = tanh(H@WK+b)  -> fp16 hi/lo planes   (M=4096)
//  z=1: qproj = Q@WQ+b        -> fp16 hi/lo planes   (M=200)
//  z=2: wql   = ql@WV+b       -> fp32                (M=50)
// Block 128x64, BK=32, 256 thr = 8 warps (4m x 2n), warp tile 32x32.
// 3 blocks/SM (smem 60KB, regs capped ~85) -> 24 warps/SM.
// ============================================================
#define PSTR 40                  // halves per smem row (80B = 16B multiple)
#define A_PL (128 * PSTR)        // A plane halves
#define B_PL (64 * PSTR)         // B plane halves
#define STG_H (2 * A_PL + 2 * B_PL)
#define PROJ_SMEM (2 * STG_H * 2)       // 61440 bytes
#define NITER 24                 // 768 / 32

__global__ void __launch_bounds__(256, 3) proj_f16_kernel(
    const __half* __restrict__ pool, __half* __restrict__ poolw,
    const float* __restrict__ WKb, const float* __restrict__ WQb,
    const float* __restrict__ WVb, float* __restrict__ wqlout)
{
    const int z = blockIdx.z;
    int M; const __half *Ah, *Al, *Bh, *Bl; const float* bias;
    if (z == 0) {
        M = 4096; Ah = pool + AH_H; Al = pool + AH_L;
        Bh = pool + WKT_H; Bl = pool + WKT_H + W_PL; bias = WKb;
    } else if (z == 1) {
        if (blockIdx.y >= 2) return;
        M = R_ROWS; Ah = pool + QH_; Al = pool + QL_;
        Bh = pool + WQT_H; Bl = pool + WQT_H + W_PL; bias = WQb;
    } else {
        if (blockIdx.y >= 1) return;
        M = C_CLS; Ah = pool + QLH_; Al = pool + QLL_;
        Bh = pool + WVT_H; Bl = pool + WVT_H + W_PL; bias = WVb;
    }

    extern __shared__ __align__(16) __half psm[];
    const uint32_t sbase = smem_u32(psm);

    const int tid = threadIdx.x;
    const int warp = tid >> 5, lane = tid & 31;
    const int wm = (warp >> 1) * 32, wn = (warp & 1) * 32;
    const int bm = blockIdx.y * 128, bn = blockIdx.x * 64;
    const int lrow = lane >> 2, lcol = lane & 3;

    // ldmatrix lane-address components
    const int a_r = lane & 15, a_c = (lane >> 4) << 3;
    const int b_r = ((lane >> 4) << 3) + (lane & 7);
    const int b_c = ((lane >> 3) & 1) << 3;

    const int crow = tid >> 2, cch = (tid & 3) * 8;  // copy indices

    const __half* srcs[4] = { Ah, Al, Bh, Bl };
    auto issue = [&](int stage, int k0) {
#pragma unroll
        for (int p = 0; p < 2; p++) {
#pragma unroll
            for (int i = 0; i < 2; i++) {
                int row = crow + i * 64;
                const __half* src = srcs[p] + (size_t)(bm + row) * D_MODEL + k0 + cch;
                uint32_t dst = sbase + (stage * STG_H + p * A_PL + row * PSTR + cch) * 2;
                cp_async16(dst, src);
            }
        }
#pragma unroll
        for (int p = 2; p < 4; p++) {
            const __half* src = srcs[p] + (size_t)(bn + crow) * D_MODEL + k0 + cch;
            uint32_t dst = sbase + (stage * STG_H + 2 * A_PL + (p - 2) * B_PL + crow * PSTR + cch) * 2;
            cp_async16(dst, src);
        }
        CP_COMMIT();
    };

    float acc[2][4][4];
#pragma unroll
    for (int mi = 0; mi < 2; mi++)
#pragma unroll
        for (int ni = 0; ni < 4; ni++)
#pragma unroll
            for (int q = 0; q < 4; q++) acc[mi][ni][q] = 0.f;

    issue(0, 0);
    issue(1, 32);

    for (int it = 0; it < NITER; it++) {
        const int s = it & 1;
        CP_WAIT1();
        __syncthreads();

        const uint32_t ahs_u = sbase + (s * STG_H) * 2;
        const uint32_t als_u = ahs_u + A_PL * 2;
        const uint32_t bhs_u = als_u + A_PL * 2;
        const uint32_t bls_u = bhs_u + B_PL * 2;

#pragma unroll
        for (int ck = 0; ck < 2; ck++) {
            const int kk = ck * 16;
            uint32_t ah[2][4], al_[2][4];
#pragma unroll
            for (int mi = 0; mi < 2; mi++) {
                const uint32_t aoff = ((wm + mi * 16 + a_r) * PSTR + kk + a_c) * 2;
                ldsm_x4(ah[mi],  ahs_u + aoff);
                ldsm_x4(al_[mi], als_u + aoff);
            }
            uint32_t bh[4][2], bl_[4][2];
#pragma unroll
            for (int nj = 0; nj < 2; nj++) {
                const uint32_t boff = ((wn + nj * 16 + b_r) * PSTR + kk + b_c) * 2;
                uint32_t q[4];
                ldsm_x4(q, bhs_u + boff);
                bh[nj * 2][0] = q[0]; bh[nj * 2][1] = q[1];
                bh[nj * 2 + 1][0] = q[2]; bh[nj * 2 + 1][1] = q[3];
                ldsm_x4(q, bls_u + boff);
                bl_[nj * 2][0] = q[0]; bl_[nj * 2][1] = q[1];
                bl_[nj * 2 + 1][0] = q[2]; bl_[nj * 2 + 1][1] = q[3];
            }
#pragma unroll
            for (int ni = 0; ni < 4; ni++)
#pragma unroll
                for (int mi = 0; mi < 2; mi++)
                    mma_f16(acc[mi][ni], ah[mi], bh[ni]);
#pragma unroll
            for (int ni = 0; ni < 4; ni++)
#pragma unroll
                for (int mi = 0; mi < 2; mi++)
                    mma_f16(acc[mi][ni], ah[mi], bl_[ni]);
#pragma unroll
            for (int ni = 0; ni < 4; ni++)
#pragma unroll
                for (int mi = 0; mi < 2; mi++)
                    mma_f16(acc[mi][ni], al_[mi], bh[ni]);
        }
        __syncthreads();

        if (it + 2 < NITER) issue(s, (it + 2) * 32);
        else CP_COMMIT();
    }

    // epilogue
    const long oh = (z == 0) ? KPH_ : QPH_;
    const long ol = (z == 0) ? KPL_ : QPL_;
#pragma unroll
    for (int mi = 0; mi < 2; mi++) {
        const int row = bm + wm + mi * 16 + lrow;
#pragma unroll
        for (int ni = 0; ni < 4; ni++) {
            const int col = bn + wn + ni * 8 + lcol * 2;
            const float b0 = bias[col], b1 = bias[col + 1];
            float v0 = acc[mi][ni][0] + b0, v1 = acc[mi][ni][1] + b1;
            float v2 = acc[mi][ni][2] + b0, v3 = acc[mi][ni][3] + b1;
            if (z == 0) {
                v0 = tanhf(v0); v1 = tanhf(v1);
                v2 = tanhf(v2); v3 = tanhf(v3);
            }
            if (z <= 1) {
                if (row < M) {
                    __half h0, l0, h1, l1;
                    split2h(v0, h0, l0); split2h(v1, h1, l1);
                    *(__half2*)&poolw[oh + (size_t)row * D_MODEL + col] = __halves2half2(h0, h1);
                    *(__half2*)&poolw[ol + (size_t)row * D_MODEL + col] = __halves2half2(l0, l1);
                }
                if (row + 8 < M) {
                    __half h2, l2, h3, l3;
                    split2h(v2, h2, l2); split2h(v3, h3, l3);
                    *(__half2*)&poolw[oh + (size_t)(row + 8) * D_MODEL + col] = __halves2half2(h2, h3);
                    *(__half2*)&poolw[ol + (size_t)(row + 8) * D_MODEL + col] = __halves2half2(l2, l3);
                }
            } else {
                if (row < M)
                    *(float2*)&wqlout[(size_t)row * D_MODEL + col] = make_float2(v0, v1);
                if (row + 8 < M)
                    *(float2*)&wqlout[(size_t)(row + 8) * D_MODEL + col] = make_float2(v2, v3);
            }
        }
    }
}

// ============================================================
// Scores GEMM (fp16x3, ldmatrix): per bz over 64-k slice
// Block 64x128, K=64 single pass, 8 warps (2x4), warp tile 32x32.
// ============================================================
#define SSTRH 72
#define SC_SMEM_B ((64 * SSTRH * 2 + 128 * SSTRH * 2) * 2)   // 55296

__global__ void __launch_bounds__(256) scores_f16_kernel(
    const __half* __restrict__ pool, float* __restrict__ scores)
{
    extern __shared__ __align__(16) __half ssm[];
    __half* Ahs = ssm;
    __half* Als = Ahs + 64 * SSTRH;
    __half* Bhs = Als + 64 * SSTRH;
    __half* Bls = Bhs + 128 * SSTRH;

    const int bz = blockIdx.z, b = bz / NH, zz = bz % NH;
    const __half* Aph = pool + QPH_ + zz * HDIM;
    const __half* Apl = pool + QPL_ + zz * HDIM;
    const __half* Bph = pool + KPH_ + (size_t)b * T_LEN * D_MODEL + zz * HDIM;
    const __half* Bpl = pool + KPL_ + (size_t)b * T_LEN * D_MODEL + zz * HDIM;
    float* Cb = scores + (size_t)bz * R_ROWS * T_LEN;

    const int tid = threadIdx.x;
    const int warp = tid >> 5, lane = tid & 31;
    const int wm = (warp >> 2) * 32, wn = (warp & 3) * 32;
    const int mbase = blockIdx.y * 64, nbase = blockIdx.x * 128;
    const int lrow = lane >> 2, lcol = lane & 3;
    const uint4 z4 = make_uint4(0u, 0u, 0u, 0u);

    const int a_r = lane & 15, a_c = (lane >> 4) << 3;
    const int b_r = ((lane >> 4) << 3) + (lane & 7);
    const int b_c = ((lane >> 3) & 1) << 3;

#pragma unroll
    for (int i = 0; i < 2; i++) {
        int fl = tid + 256 * i, row = fl >> 3, ch = fl & 7;
        bool ok = (mbase + row) < R_ROWS;
        size_t ga = (size_t)(mbase + row) * D_MODEL + ch * 8;
        *(uint4*)&Ahs[row * SSTRH + ch * 8] = ok ? *(const uint4*)&Aph[ga] : z4;
        *(uint4*)&Als[row * SSTRH + ch * 8] = ok ? *(const uint4*)&Apl[ga] : z4;
    }
#pragma unroll
    for (int i = 0; i < 4; i++) {
        int fl = tid + 256 * i, row = fl >> 3, ch = fl & 7;
        size_t gb = (size_t)(nbase + row) * D_MODEL + ch * 8;
        *(uint4*)&Bhs[row * SSTRH + ch * 8] = *(const uint4*)&Bph[gb];
        *(uint4*)&Bls[row * SSTRH + ch * 8] = *(const uint4*)&Bpl[gb];
    }
    __syncthreads();

    const uint32_t ahs_u = smem_u32(Ahs), als_u = smem_u32(Als);
    const uint32_t bhs_u = smem_u32(Bhs), bls_u = smem_u32(Bls);

    float acc[2][4][4];
#pragma unroll
    for (int mi = 0; mi < 2; mi++)
#pragma unroll
        for (int ni = 0; ni < 4; ni++)
#pragma unroll
            for (int q = 0; q < 4; q++) acc[mi][ni][q] = 0.f;

#pragma unroll
    for (int ck = 0; ck < 4; ck++) {
        const int kk = ck * 16;
        uint32_t ah[2][4], al_[2][4];
#pragma unroll
        for (int mi = 0; mi < 2; mi++) {
            const uint32_t aoff = ((wm + mi * 16 + a_r) * SSTRH + kk + a_c) * 2;
            ldsm_x4(ah[mi],  ahs_u + aoff);
            ldsm_x4(al_[mi], als_u + aoff);
        }
        uint32_t bh[4][2], bl_[4][2];
#pragma unroll
        for (int nj = 0; nj < 2; nj++) {
            const uint32_t boff = ((wn + nj * 16 + b_r) * SSTRH + kk + b_c) * 2;
            uint32_t q[4];
            ldsm_x4(q, bhs_u + boff);
            bh[nj * 2][0] = q[0]; bh[nj * 2][1] = q[1];
            bh[nj * 2 + 1][0] = q[2]; bh[nj * 2 + 1][1] = q[3];
            ldsm_x4(q, bls_u + boff);
            bl_[nj * 2][0] = q[0]; bl_[nj * 2][1] = q[1];
            bl_[nj * 2 + 1][0] = q[2]; bl_[nj * 2 + 1][1] = q[3];
        }
#pragma unroll
        for (int ni = 0; ni < 4; ni++)
#pragma unroll
            for (int mi = 0; mi < 2; mi++)
                mma_f16(acc[mi][ni], ah[mi], bh[ni]);
#pragma unroll
        for (int ni = 0; ni < 4; ni++)
#pragma unroll
            for (int mi = 0; mi < 2; mi++)
                mma_f16(acc[mi][ni], ah[mi], bl_[ni]);
#pragma unroll
        for (int ni = 0; ni < 4; ni++)
#pragma unroll
            for (int mi = 0; mi < 2; mi++)
                mma_f16(acc[mi][ni], al_[mi], bh[ni]);
    }

#pragma unroll
    for (int mi = 0; mi < 2; mi++) {
        const int row = mbase + wm + mi * 16 + lrow;
#pragma unroll
        for (int ni = 0; ni < 4; ni++) {
            const int col = nbase + wn + ni * 8 + lcol * 2;
            if (row < R_ROWS)
                *(float2*)&Cb[(size_t)row * T_LEN + col] =
                    make_float2(acc[mi][ni][0], acc[mi][ni][1]);
            if (row + 8 < R_ROWS)
                *(float2*)&Cb[(size_t)(row + 8) * T_LEN + col] =
                    make_float2(acc[mi][ni][2], acc[mi][ni][3]);
        }
    }
}

// ============================================================
// Softmax over t for 4 synonym rows -> combined mean weights
// ============================================================
__global__ void __launch_bounds__(128) softmax_combine_kernel(
    const float* __restrict__ scores, float* __restrict__ w)
{
    __shared__ float ex[4][1024];
    __shared__ float invl[4];
    const int blk = blockIdx.x;
    const int bz = blk / C_CLS, c = blk % C_CLS;
    const int warp = threadIdx.x >> 5, lane = threadIdx.x & 31;

    const float* row = scores + ((size_t)bz * R_ROWS + c * 4 + warp) * T_LEN;

    float m = -INFINITY;
    for (int t = lane; t < T_LEN; t += 32) m = fmaxf(m, row[t]);
#pragma unroll
    for (int o = 16; o > 0; o >>= 1) m = fmaxf(m, __shfl_xor_sync(0xffffffffu, m, o));

    float ssum = 0.f;
    for (int t = lane; t < T_LEN; t += 32) {
        float e = expf(row[t] - m);
        ex[warp][t] = e;
        ssum += e;
    }
#pragma unroll
    for (int o = 16; o > 0; o >>= 1) ssum += __shfl_xor_sync(0xffffffffu, ssum, o);
    if (lane == 0) invl[warp] = 0.25f / ssum;
    __syncthreads();

    float* wr = w + ((size_t)bz * C_CLS + c) * T_LEN;
    for (int t = threadIdx.x; t < T_LEN; t += 128)
        wr[t] = ex[0][t] * invl[0] + ex[1][t] * invl[1]
              + ex[2][t] * invl[2] + ex[3][t] * invl[3];
}

// ============================================================
// Fused m2 + final (smem pad 68 = 272B stride, 16B multiple)
// ============================================================
__global__ void __launch_bounds__(256) m2_fused_kernel(
    const float* __restrict__ H, const float* __restrict__ wql,
    const float* __restrict__ w, float* __restrict__ out)
{
    const int bz = blockIdx.z;
    const int b = bz / NH, z = bz % NH;
    const int tbase = blockIdx.y * 64;

    __shared__ float Qs[64][68];
    __shared__ float Ks[64][68];

    const int tid = threadIdx.x;

#pragma unroll
    for (int i = 0; i < 4; i++) {
        int fl = tid + 256 * i;
        int row = fl >> 4;
        int hc = (fl & 15) * 4;
        float4 v = *(const float4*)&H[(size_t)(b * T_LEN + tbase + row) * D_MODEL + z * HDIM + hc];
        Qs[hc + 0][row] = tanhf(v.x); Qs[hc + 1][row] = tanhf(v.y);
        Qs[hc + 2][row] = tanhf(v.z); Qs[hc + 3][row] = tanhf(v.w);
    }
#pragma unroll
    for (int i = 0; i < 4; i++) {
        int fl = tid + 256 * i;
        int row = fl >> 4;
        int hc = (fl & 15) * 4;
        float4 v = make_float4(0.f, 0.f, 0.f, 0.f);
        if (row < C_CLS)
            v = *(const float4*)&wql[(size_t)row * D_MODEL + z * HDIM + hc];
        Ks[hc + 0][row] = v.x; Ks[hc + 1][row] = v.y;
        Ks[hc + 2][row] = v.z; Ks[hc + 3][row] = v.w;
    }
    __syncthreads();

    const int tx = tid & 15, ty = tid >> 4;
    float acc[4][4];
#pragma unroll
    for (int i = 0; i < 4; i++)
#pragma unroll
        for (int j = 0; j < 4; j++) acc[i][j] = 0.f;

#pragma unroll
    for (int h = 0; h < 64; h++) {
        float ar[4], br[4];
        *(float4*)&ar[0] = *(float4*)&Qs[h][ty * 4];
        *(float4*)&br[0] = *(float4*)&Ks[h][tx * 4];
#pragma unroll
        for (int i = 0; i < 4; i++)
#pragma unroll
            for (int j = 0; j < 4; j++)
                acc[i][j] = fmaf(ar[i], br[j], acc[i][j]);
    }
    __syncthreads();

    float* pm = &Qs[0][0];
    float p[4];
#pragma unroll
    for (int j = 0; j < 4; j++) {
        const int c = tx * 4 + j;
        p[j] = 0.f;
        if (c < C_CLS) {
            float4 wv = *(const float4*)&w[((size_t)bz * C_CLS + c) * T_LEN + tbase + ty * 4];
            p[j] = acc[0][j] * wv.x + acc[1][j] * wv.y
                 + acc[2][j] * wv.z + acc[3][j] * wv.w;
        }
        pm[ty * 64 + tx * 4 + j] = p[j];
    }
    __syncthreads();

    if (tid < 64 && tid < C_CLS) {
        float s = 0.f;
#pragma unroll
        for (int r = 0; r < 16; r++) s += pm[r * 64 + tid];
        atomicAdd(&out[b * C_CLS + tid], s);
    }
}

// ============================================================
extern "C" void kernel_launch(void* const* d_in, const int* in_sizes, int n_in,
                              void* d_out, int out_size)
{
    const float* Q   = (const float*)d_in[0];
    const float* H   = (const float*)d_in[1];
    const float* ql  = (const float*)d_in[2];
    const float* WQw = (const float*)d_in[3];
    const float* WQb = (const float*)d_in[4];
    const float* WKw = (const float*)d_in[5];
    const float* WKb = (const float*)d_in[6];
    const float* WVw = (const float*)d_in[7];
    const float* WVb = (const float*)d_in[8];
    float* out = (float*)d_out;

    __half* pool;
    float *wql, *scores, *w;
    cudaGetSymbolAddress((void**)&pool,   g_hf);
    cudaGetSymbolAddress((void**)&wql,    g_wql);
    cudaGetSymbolAddress((void**)&scores, g_scores);
    cudaGetSymbolAddress((void**)&w,      g_w);

    cudaFuncSetAttribute(proj_f16_kernel,
                         cudaFuncAttributeMaxDynamicSharedMemorySize, PROJ_SMEM);
    cudaFuncSetAttribute(scores_f16_kernel,
                         cudaFuncAttributeMaxDynamicSharedMemorySize, SC_SMEM_B);

    zero_out_kernel<<<1, 256>>>(out);

    split_all_kernel<<<(N_H + N_Q + N_QL + 255) / 256, 256>>>(H, Q, ql, pool);
    split_transpose_kernel<<<dim3(24, 24, 3), 256>>>(WKw, WQw, WVw, pool);

    proj_f16_kernel<<<dim3(12, 32, 3), 256, PROJ_SMEM>>>(pool, pool, WKb, WQb, WVb, wql);

    scores_f16_kernel<<<dim3(8, 4, BZ), 256, SC_SMEM_B>>>(pool, scores);

    softmax_combine_kernel<<<BZ * C_CLS, 128>>>(scores, w);

    m2_fused_kernel<<<dim3(1, 16, BZ), 256>>>(H, wql, w, out);
}